// round 3
// baseline (speedup 1.0000x reference)
#include <cuda_runtime.h>
#include <cstdint>

#define MAX_NODES 50000
#define LAT       100
#define NGRAPH    256
#define H2        200
#define NCLASS    55
#define MAX_EDGES 800000

typedef unsigned long long u64;

// ---------------- scratch (device globals) ---------------------------------
__device__ __align__(16) float g_bufA[MAX_NODES * LAT];
__device__ __align__(16) float g_bufB[MAX_NODES * LAT];
__device__ __align__(16) float g_inv_out[MAX_NODES];
__device__ __align__(16) float g_inv_in[MAX_NODES];
__device__ __align__(16) int   g_off[MAX_NODES + 16];
__device__ __align__(16) int   g_cur[MAX_NODES];
__device__ __align__(16) int   g_csr[MAX_EDGES];

// packed zero region: [0,50000) out_deg(f32), [50000,100000) deg_in(i32),
// [100000,151200) pool, [151200,151456) cnt
#define ZR_OUTDEG 0
#define ZR_DEGIN  50000
#define ZR_POOL   100000
#define ZR_CNT    151200
#define ZR_TOTAL  151456
__device__ __align__(16) float g_zregion[ZR_TOTAL];

// ---------------- f32x2 packed math helpers --------------------------------
__device__ __forceinline__ u64 pack_dup(float a) {
    u64 r; asm("mov.b64 %0, {%1, %1};" : "=l"(r) : "f"(a)); return r;
}
__device__ __forceinline__ void ffma2(u64& d, u64 a, u64 b) {
    asm("fma.rn.f32x2 %0, %1, %2, %0;" : "+l"(d) : "l"(a), "l"(b));
}
__device__ __forceinline__ float2 unpack2(u64 v) {
    float2 f; asm("mov.b64 {%0, %1}, %2;" : "=f"(f.x), "=f"(f.y) : "l"(v)); return f;
}

// ---------------- small kernels -------------------------------------------
__global__ void zero_kernel(float4* p, int n4) {
    int i = blockIdx.x * blockDim.x + threadIdx.x;
    float4 z = make_float4(0.f, 0.f, 0.f, 0.f);
    for (; i < n4; i += gridDim.x * blockDim.x) p[i] = z;
}

__global__ void degree_kernel(const int* __restrict__ src, const int* __restrict__ dst, int E) {
    float* out_deg = g_zregion + ZR_OUTDEG;
    int*   deg_in  = (int*)(g_zregion + ZR_DEGIN);
    int i = blockIdx.x * blockDim.x + threadIdx.x;
    if (i < E) {
        atomicAdd(&out_deg[src[i]], 1.0f);
        atomicAdd(&deg_in[dst[i]], 1);
    }
}

// single-block exclusive scan of deg_in -> off/cur; also inv_in/inv_out rsqrt
__global__ void scan_kernel(int n) {
    __shared__ int warp_sums[32];
    __shared__ int s_carry;
    const float* out_deg = g_zregion + ZR_OUTDEG;
    const int*   deg_in  = (const int*)(g_zregion + ZR_DEGIN);
    int tid = threadIdx.x, lane = tid & 31, warp = tid >> 5;
    if (tid == 0) s_carry = 0;
    __syncthreads();
    for (int base = 0; base < n; base += 1024) {
        int i = base + tid;
        int v = (i < n) ? deg_in[i] : 0;
        if (i < n) {
            g_inv_in[i]  = rsqrtf(fmaxf((float)v, 1.0f));
            g_inv_out[i] = rsqrtf(fmaxf(out_deg[i], 1.0f));
        }
        int s = v;
#pragma unroll
        for (int d = 1; d < 32; d <<= 1) {
            int t = __shfl_up_sync(0xffffffffu, s, d);
            if (lane >= d) s += t;
        }
        if (lane == 31) warp_sums[warp] = s;
        __syncthreads();
        if (warp == 0) {
            int ws = warp_sums[lane];
#pragma unroll
            for (int d = 1; d < 32; d <<= 1) {
                int t = __shfl_up_sync(0xffffffffu, ws, d);
                if (lane >= d) ws += t;
            }
            warp_sums[lane] = ws;
        }
        __syncthreads();
        int wprefix = (warp > 0) ? warp_sums[warp - 1] : 0;
        int incl = s + wprefix;
        int excl = incl - v + s_carry;
        if (i < n) { g_off[i] = excl; g_cur[i] = excl; }
        int chunk_total = warp_sums[31];
        __syncthreads();
        if (tid == 0) s_carry += chunk_total;
        __syncthreads();
    }
    if (tid == 0) g_off[n] = s_carry;
}

__global__ void scatter_kernel(const int* __restrict__ src, const int* __restrict__ dst, int E) {
    int i = blockIdx.x * blockDim.x + threadIdx.x;
    if (i < E) {
        int p = atomicAdd(&g_cur[dst[i]], 1);
        g_csr[p] = src[i];
    }
}

__global__ void count_kernel(const int* __restrict__ gid, int n) {
    float* cnt = g_zregion + ZR_CNT;
    int i = blockIdx.x * blockDim.x + threadIdx.x;
    if (i < n) atomicAdd(&cnt[gid[i]], 1.0f);
}

// ---------------- CSR propagation: agg[i,:] = sum_{e in in(i)} xs[csr[e],:] -
__global__ void prop_csr_kernel(const float4* __restrict__ xs,
                                float4* __restrict__ agg, int n) {
    int warp = (blockIdx.x * blockDim.x + threadIdx.x) >> 5;
    int lane = threadIdx.x & 31;
    if (warp >= n) return;
    int b = g_off[warp], e = g_off[warp + 1];
    bool act = lane < 25;
    float4 a0 = make_float4(0.f, 0.f, 0.f, 0.f);
    float4 a1 = a0, a2 = a0, a3 = a0;
    unsigned base = (unsigned)lane;
    int k = b;
    for (; k + 4 <= e; k += 4) {
        int s0 = g_csr[k], s1 = g_csr[k + 1], s2 = g_csr[k + 2], s3 = g_csr[k + 3];
        if (act) {
            float4 v0 = xs[(unsigned)s0 * 25u + base];
            float4 v1 = xs[(unsigned)s1 * 25u + base];
            float4 v2 = xs[(unsigned)s2 * 25u + base];
            float4 v3 = xs[(unsigned)s3 * 25u + base];
            a0.x += v0.x; a0.y += v0.y; a0.z += v0.z; a0.w += v0.w;
            a1.x += v1.x; a1.y += v1.y; a1.z += v1.z; a1.w += v1.w;
            a2.x += v2.x; a2.y += v2.y; a2.z += v2.z; a2.w += v2.w;
            a3.x += v3.x; a3.y += v3.y; a3.z += v3.z; a3.w += v3.w;
        }
    }
    for (; k < e; k++) {
        int s0 = g_csr[k];
        if (act) {
            float4 v0 = xs[(unsigned)s0 * 25u + base];
            a0.x += v0.x; a0.y += v0.y; a0.z += v0.z; a0.w += v0.w;
        }
    }
    if (act) {
        a0.x += a1.x + a2.x + a3.x;
        a0.y += a1.y + a2.y + a3.y;
        a0.z += a1.z + a2.z + a3.z;
        a0.w += a1.w + a2.w + a3.w;
        agg[(unsigned)warp * 25u + base] = a0;
    }
}

// ---------------- GEMM: C = ((sin .* A) @ W + b) .* sout  (or pool-atomic) -
// Packed f32x2 accumulators: each FFMA2 does 2 FMAs on the FMA pipe.
template <int N, bool POOL>
__global__ void gemm_kernel(const float* __restrict__ A,
                            const float* __restrict__ W,
                            const float* __restrict__ bias,
                            const float* __restrict__ sin_,
                            const float* __restrict__ sout,
                            float* __restrict__ Cout,
                            const int* __restrict__ gid,
                            int M, int K) {
    extern __shared__ float Wsh[];
    constexpr int CPL = N / 25;        // 4 or 8 cols per lane
    constexpr int PPL = CPL / 2;       // packed pairs per lane: 2 or 4
    int tid = threadIdx.x;
    {
        int tot4 = (K * N) >> 2;
        const float4* W4 = (const float4*)W;
        float4* Wsh4 = (float4*)Wsh;
        for (int i = tid; i < tot4; i += blockDim.x) Wsh4[i] = W4[i];
    }
    __syncthreads();

    int warp = tid >> 5, lane = tid & 31;
    int c0 = lane * CPL;
    bool active = lane < 25;

    for (int rbase = (blockIdx.x * 8 + warp) * 4; rbase < M; rbase += gridDim.x * 32) {
        u64 acc[4][PPL];
#pragma unroll
        for (int r = 0; r < 4; r++)
#pragma unroll
            for (int j = 0; j < PPL; j++) acc[r][j] = 0ull;

        float sc[4];
#pragma unroll
        for (int r = 0; r < 4; r++) {
            int row = rbase + r;
            sc[r] = (row < M) ? (sin_ ? sin_[row] : 1.0f) : 0.0f;
        }

        int k0 = 0;
        for (; k0 + 32 <= K; k0 += 32) {
            float a[4];
#pragma unroll
            for (int r = 0; r < 4; r++) {
                int row = rbase + r;
                a[r] = (row < M) ? A[row * K + k0 + lane] * sc[r] : 0.f;
            }
#pragma unroll 8
            for (int t = 0; t < 32; t++) {
                u64 ad[4];
#pragma unroll
                for (int r = 0; r < 4; r++)
                    ad[r] = pack_dup(__shfl_sync(0xffffffffu, a[r], t));
                if (active) {
#pragma unroll
                    for (int j = 0; j < PPL; j += 2) {
                        ulonglong2 wv = *(const ulonglong2*)&Wsh[(k0 + t) * N + c0 + j * 2];
#pragma unroll
                        for (int r = 0; r < 4; r++) {
                            ffma2(acc[r][j],     ad[r], wv.x);
                            ffma2(acc[r][j + 1], ad[r], wv.y);
                        }
                    }
                }
            }
        }
        if (k0 < K) {
            int rem = K - k0;
            float a[4];
#pragma unroll
            for (int r = 0; r < 4; r++) {
                int row = rbase + r;
                a[r] = (row < M && lane < rem) ? A[row * K + k0 + lane] * sc[r] : 0.f;
            }
            for (int t = 0; t < rem; t++) {
                u64 ad[4];
#pragma unroll
                for (int r = 0; r < 4; r++)
                    ad[r] = pack_dup(__shfl_sync(0xffffffffu, a[r], t));
                if (active) {
#pragma unroll
                    for (int j = 0; j < PPL; j += 2) {
                        ulonglong2 wv = *(const ulonglong2*)&Wsh[(k0 + t) * N + c0 + j * 2];
#pragma unroll
                        for (int r = 0; r < 4; r++) {
                            ffma2(acc[r][j],     ad[r], wv.x);
                            ffma2(acc[r][j + 1], ad[r], wv.y);
                        }
                    }
                }
            }
        }

        if (active) {
            if (!POOL) {
#pragma unroll
                for (int r = 0; r < 4; r++) {
                    int row = rbase + r;
                    if (row < M) {
                        float so = sout ? sout[row] : 1.0f;
#pragma unroll
                        for (int j = 0; j < PPL; j += 2) {
                            float4 bv = *(const float4*)&bias[c0 + j * 2];
                            float2 p0 = unpack2(acc[r][j]);
                            float2 p1 = unpack2(acc[r][j + 1]);
                            float4 v;
                            v.x = (p0.x + bv.x) * so;
                            v.y = (p0.y + bv.y) * so;
                            v.z = (p1.x + bv.z) * so;
                            v.w = (p1.y + bv.w) * so;
                            *(float4*)&Cout[row * N + c0 + j * 2] = v;
                        }
                    }
                }
            } else {
#pragma unroll
                for (int r = 0; r < 4; r++) {
                    int row = rbase + r;
                    if (row < M) {
                        int g = gid[row];
#pragma unroll
                        for (int j = 0; j < PPL; j += 2) {
                            float4 bv = *(const float4*)&bias[c0 + j * 2];
                            float2 p0 = unpack2(acc[r][j]);
                            float2 p1 = unpack2(acc[r][j + 1]);
                            float x0 = p0.x + bv.x;
                            float x1 = p0.y + bv.y;
                            float x2 = p1.x + bv.z;
                            float x3 = p1.y + bv.w;
                            float* p = &Cout[g * N + c0 + j * 2];
                            asm volatile("red.global.add.v4.f32 [%0], {%1,%2,%3,%4};"
                                         :: "l"(p), "f"(x0), "f"(x1), "f"(x2), "f"(x3)
                                         : "memory");
                        }
                    }
                }
            }
        }
    }
}

// ---------------- final: out[g,c] = (pool[g,:]/cnt[g]) @ Wc + bc ----------
__global__ void final_kernel(const float* __restrict__ Wc, const float* __restrict__ bc,
                             float* __restrict__ out, int K2, int C) {
    __shared__ float p[H2];
    const float* pool = g_zregion + ZR_POOL;
    const float* cnt  = g_zregion + ZR_CNT;
    int g = blockIdx.x;
    float invc = 1.0f / fmaxf(cnt[g], 1.0f);
    for (int i = threadIdx.x; i < K2; i += blockDim.x) p[i] = pool[g * K2 + i] * invc;
    __syncthreads();
    int c = threadIdx.x;
    if (c < C) {
        float acc = bc[c];
        for (int k = 0; k < K2; k++) acc += p[k] * Wc[k * C + c];
        out[g * C + c] = acc;
    }
}

// ---------------- launch ---------------------------------------------------
extern "C" void kernel_launch(void* const* d_in, const int* in_sizes, int n_in,
                              void* d_out, int out_size) {
    const float* fsnet = (const float*)d_in[0];
    const int*   src   = (const int*)d_in[1];
    const int*   dst   = (const int*)d_in[2];
    const int*   gid   = (const int*)d_in[3];
    const float* W_ext = (const float*)d_in[4];
    const float* b_ext = (const float*)d_in[5];
    const float* W1    = (const float*)d_in[6];
    const float* b1    = (const float*)d_in[7];
    const float* W2    = (const float*)d_in[8];
    const float* b2    = (const float*)d_in[9];
    const float* Wc    = (const float*)d_in[10];
    const float* bc    = (const float*)d_in[11];
    float* out = (float*)d_out;

    int n   = in_sizes[3];
    int E   = in_sizes[1];
    int RAW = in_sizes[4] / LAT;

    float *bufA, *bufB, *inv_out, *inv_in, *zreg, *pool;
    cudaGetSymbolAddress((void**)&bufA,    g_bufA);
    cudaGetSymbolAddress((void**)&bufB,    g_bufB);
    cudaGetSymbolAddress((void**)&inv_out, g_inv_out);
    cudaGetSymbolAddress((void**)&inv_in,  g_inv_in);
    cudaGetSymbolAddress((void**)&zreg,    g_zregion);
    pool = zreg + ZR_POOL;

    cudaFuncSetAttribute(gemm_kernel<100, false>,
                         cudaFuncAttributeMaxDynamicSharedMemorySize, RAW * LAT * 4);
    cudaFuncSetAttribute(gemm_kernel<200, true>,
                         cudaFuncAttributeMaxDynamicSharedMemorySize, LAT * H2 * 4);

    // 1. zero packed scratch (degrees + pool + cnt)
    zero_kernel<<<148, 256>>>((float4*)zreg, ZR_TOTAL / 4);

    // 2. degrees
    degree_kernel<<<(E + 255) / 256, 256>>>(src, dst, E);

    // 3. offsets + rsqrt scaling factors
    scan_kernel<<<1, 1024>>>(n);

    // 4. CSR scatter (by dst)
    scatter_kernel<<<(E + 255) / 256, 256>>>(src, dst, E);

    // per-graph node counts (independent)
    count_kernel<<<(n + 255) / 256, 256>>>(gid, n);

    // 5. xs0 = (fsnet @ W_ext + b_ext) * inv_sqrt_out -> bufA
    gemm_kernel<100, false><<<296, 256, RAW * LAT * 4>>>(
        fsnet, W_ext, b_ext, nullptr, inv_out, bufA, nullptr, n, RAW);

    // 6. prop1
    int pblocks = (n * 32 + 255) / 256;
    prop_csr_kernel<<<pblocks, 256>>>((const float4*)bufA, (float4*)bufB, n);

    // 7. xs1 = ((bufB * inv_in) @ W1 + b1) * inv_out -> bufA
    gemm_kernel<100, false><<<592, 256, LAT * LAT * 4>>>(
        bufB, W1, b1, inv_in, inv_out, bufA, nullptr, n, LAT);

    // 8. prop2
    prop_csr_kernel<<<pblocks, 256>>>((const float4*)bufA, (float4*)bufB, n);

    // 9. h2 pooled by graph into pool (atomics)
    gemm_kernel<200, true><<<296, 256, LAT * H2 * 4>>>(
        bufB, W2, b2, inv_in, nullptr, pool, gid, n, LAT);

    // 10. out = (pool / cnt) @ Wc + bc
    final_kernel<<<NGRAPH, 64>>>(Wc, bc, out, H2, NCLASS);
}

// round 4
// speedup vs baseline: 1.4236x; 1.4236x over previous
#include <cuda_runtime.h>
#include <cstdint>

#define MAX_NODES 50000
#define LAT       100
#define NGRAPH    256
#define H2        200
#define NCLASS    55
#define MAX_EDGES 800000

typedef unsigned long long u64;

// ---------------- scratch (device globals) ---------------------------------
__device__ __align__(16) float g_bufA[MAX_NODES * LAT];   // x0 * inv_out
__device__ __align__(16) float g_bufB[MAX_NODES * LAT];   // P(x0) * inv_in * inv_out
__device__ __align__(16) float g_inv_out[MAX_NODES];
__device__ __align__(16) float g_inv_in[MAX_NODES];
__device__ __align__(16) float g_s1[MAX_NODES];           // inv_in * inv_out
__device__ __align__(16) int   g_off[MAX_NODES + 16];
__device__ __align__(16) int   g_cur[MAX_NODES];
__device__ __align__(16) int   g_csr[MAX_EDGES];
__device__ __align__(16) int   g_bsum[80];
__device__ __align__(16) int   g_bpre[80];
__device__ __align__(16) float g_W12[LAT * H2];           // W1 @ W2
__device__ __align__(16) float g_Wfin[LAT * NCLASS];      // W1 @ W2 @ Wc
__device__ __align__(16) float g_v1[64];                  // b1 @ W2 @ Wc
__device__ __align__(16) float g_c0[64];                  // b2 @ Wc + bc

// packed zero region: out_deg(f32) | deg_in(i32) | poolX | poolD | cnt
#define ZR_OUTDEG 0
#define ZR_DEGIN  50000
#define ZR_POOLX  100000
#define ZR_POOLD  125600
#define ZR_CNT    125856
#define ZR_TOTAL  126112
__device__ __align__(16) float g_zregion[ZR_TOTAL];

// ---------------- f32x2 packed math helpers --------------------------------
__device__ __forceinline__ u64 pack_dup(float a) {
    u64 r; asm("mov.b64 %0, {%1, %1};" : "=l"(r) : "f"(a)); return r;
}
__device__ __forceinline__ void ffma2(u64& d, u64 a, u64 b) {
    asm("fma.rn.f32x2 %0, %1, %2, %0;" : "+l"(d) : "l"(a), "l"(b));
}
__device__ __forceinline__ float2 unpack2(u64 v) {
    float2 f; asm("mov.b64 {%0, %1}, %2;" : "=f"(f.x), "=f"(f.y) : "l"(v)); return f;
}

// ---------------- small kernels -------------------------------------------
__global__ void zero_kernel(float4* p, int n4) {
    int i = blockIdx.x * blockDim.x + threadIdx.x;
    float4 z = make_float4(0.f, 0.f, 0.f, 0.f);
    for (; i < n4; i += gridDim.x * blockDim.x) p[i] = z;
}

__global__ void degree_kernel(const int* __restrict__ src, const int* __restrict__ dst, int E) {
    float* out_deg = g_zregion + ZR_OUTDEG;
    int*   deg_in  = (int*)(g_zregion + ZR_DEGIN);
    int i = blockIdx.x * blockDim.x + threadIdx.x;
    if (i < E) {
        atomicAdd(&out_deg[src[i]], 1.0f);
        atomicAdd(&deg_in[dst[i]], 1);
    }
}

// scanA: per-chunk reduce of deg_in; also rsqrt factors + per-graph counts
__global__ void scanA_kernel(const int* __restrict__ gid, int n) {
    __shared__ int wsum[32];
    const float* out_deg = g_zregion + ZR_OUTDEG;
    const int*   deg_in  = (const int*)(g_zregion + ZR_DEGIN);
    float* cnt = g_zregion + ZR_CNT;
    int tid = threadIdx.x, lane = tid & 31, warp = tid >> 5;
    int i = blockIdx.x * 1024 + tid;
    int v = 0;
    if (i < n) {
        v = deg_in[i];
        float ii = rsqrtf(fmaxf((float)v, 1.0f));
        float io = rsqrtf(fmaxf(out_deg[i], 1.0f));
        g_inv_in[i]  = ii;
        g_inv_out[i] = io;
        g_s1[i]      = ii * io;
        atomicAdd(&cnt[gid[i]], 1.0f);
    }
    int s = v;
#pragma unroll
    for (int d = 16; d > 0; d >>= 1) s += __shfl_down_sync(0xffffffffu, s, d);
    if (lane == 0) wsum[warp] = s;
    __syncthreads();
    if (warp == 0) {
        int t = (lane < 32) ? wsum[lane] : 0;
#pragma unroll
        for (int d = 16; d > 0; d >>= 1) t += __shfl_down_sync(0xffffffffu, t, d);
        if (lane == 0) g_bsum[blockIdx.x] = t;
    }
}

// scanB: exclusive scan of block sums (tiny)
__global__ void scanB_kernel(int nb, int n) {
    __shared__ int s[80];
    int tid = threadIdx.x;
    if (tid < nb) s[tid] = g_bsum[tid];
    __syncthreads();
    if (tid == 0) {
        int run = 0;
        for (int b = 0; b < nb; b++) { int t = s[b]; s[b] = run; run += t; }
        g_off[n] = run;
    }
    __syncthreads();
    if (tid < nb) g_bpre[tid] = s[tid];
}

// scanC: local exclusive scan + block prefix -> off/cur
__global__ void scanC_kernel(int n) {
    __shared__ int wsum[32];
    const int* deg_in = (const int*)(g_zregion + ZR_DEGIN);
    int tid = threadIdx.x, lane = tid & 31, warp = tid >> 5;
    int i = blockIdx.x * 1024 + tid;
    int v = (i < n) ? deg_in[i] : 0;
    int s = v;
#pragma unroll
    for (int d = 1; d < 32; d <<= 1) {
        int t = __shfl_up_sync(0xffffffffu, s, d);
        if (lane >= d) s += t;
    }
    if (lane == 31) wsum[warp] = s;
    __syncthreads();
    if (warp == 0) {
        int ws = wsum[lane];
#pragma unroll
        for (int d = 1; d < 32; d <<= 1) {
            int t = __shfl_up_sync(0xffffffffu, ws, d);
            if (lane >= d) ws += t;
        }
        wsum[lane] = ws;
    }
    __syncthreads();
    int wpre = (warp > 0) ? wsum[warp - 1] : 0;
    int excl = s - v + wpre + g_bpre[blockIdx.x];
    if (i < n) { g_off[i] = excl; g_cur[i] = excl; }
}

__global__ void scatter_kernel(const int* __restrict__ src, const int* __restrict__ dst, int E) {
    int i = blockIdx.x * blockDim.x + threadIdx.x;
    if (i < E) {
        int p = atomicAdd(&g_cur[dst[i]], 1);
        g_csr[p] = src[i];
    }
}

// ---------------- CSR propagation -----------------------------------------
// agg_i = (sum over in-edges of xs[src]) * scale_i ; write row or pool-reduce
template <bool POOL>
__global__ void prop_csr_kernel(const float4* __restrict__ xs,
                                float4* __restrict__ agg,
                                const float* __restrict__ scale,
                                const int* __restrict__ gid, int n) {
    int node = (blockIdx.x * blockDim.x + threadIdx.x) >> 5;
    int lane = threadIdx.x & 31;
    if (node >= n) return;
    int b = g_off[node], e = g_off[node + 1];
    bool act = lane < 25;
    float4 a0 = make_float4(0.f, 0.f, 0.f, 0.f);
    float4 a1 = a0, a2 = a0, a3 = a0;
    unsigned base = (unsigned)lane;
    int k = b;
    for (; k + 4 <= e; k += 4) {
        int s0 = g_csr[k], s1 = g_csr[k + 1], s2 = g_csr[k + 2], s3 = g_csr[k + 3];
        if (act) {
            float4 v0 = xs[(unsigned)s0 * 25u + base];
            float4 v1 = xs[(unsigned)s1 * 25u + base];
            float4 v2 = xs[(unsigned)s2 * 25u + base];
            float4 v3 = xs[(unsigned)s3 * 25u + base];
            a0.x += v0.x; a0.y += v0.y; a0.z += v0.z; a0.w += v0.w;
            a1.x += v1.x; a1.y += v1.y; a1.z += v1.z; a1.w += v1.w;
            a2.x += v2.x; a2.y += v2.y; a2.z += v2.z; a2.w += v2.w;
            a3.x += v3.x; a3.y += v3.y; a3.z += v3.z; a3.w += v3.w;
        }
    }
    for (; k < e; k++) {
        int s0 = g_csr[k];
        if (act) {
            float4 v0 = xs[(unsigned)s0 * 25u + base];
            a0.x += v0.x; a0.y += v0.y; a0.z += v0.z; a0.w += v0.w;
        }
    }
    if (act) {
        float sc = scale[node];
        float x = (a0.x + a1.x + a2.x + a3.x) * sc;
        float y = (a0.y + a1.y + a2.y + a3.y) * sc;
        float z = (a0.z + a1.z + a2.z + a3.z) * sc;
        float w = (a0.w + a1.w + a2.w + a3.w) * sc;
        if (!POOL) {
            agg[(unsigned)node * 25u + base] = make_float4(x, y, z, w);
        } else {
            float* poolX = g_zregion + ZR_POOLX;
            float* p = poolX + (unsigned)gid[node] * 100u + base * 4u;
            asm volatile("red.global.add.v4.f32 [%0], {%1,%2,%3,%4};"
                         :: "l"(p), "f"(x), "f"(y), "f"(z), "f"(w)
                         : "memory");
        }
    }
}

// ---------------- d~ = P(ones), pooled by graph ----------------------------
__global__ void dtilde_kernel(const int* __restrict__ gid, int n) {
    int node = (blockIdx.x * blockDim.x + threadIdx.x) >> 5;
    int lane = threadIdx.x & 31;
    if (node >= n) return;
    int b = g_off[node], e = g_off[node + 1];
    float s = 0.f;
    for (int k = b + lane; k < e; k += 32) s += g_inv_out[g_csr[k]];
#pragma unroll
    for (int d = 16; d > 0; d >>= 1) s += __shfl_down_sync(0xffffffffu, s, d);
    if (lane == 0) {
        float* poolD = g_zregion + ZR_POOLD;
        atomicAdd(&poolD[gid[node]], s * g_inv_in[node]);
    }
}

// ---------------- GEMM0: C = (A @ W + b) .* sout  (f32x2 accumulators) -----
__global__ void gemm0_kernel(const float* __restrict__ A,
                             const float* __restrict__ W,
                             const float* __restrict__ bias,
                             const float* __restrict__ sout,
                             float* __restrict__ Cout,
                             int M, int K) {
    extern __shared__ float Wsh[];
    constexpr int N = LAT;   // 100
    constexpr int PPL = 2;   // 4 cols per lane = 2 packed pairs
    int tid = threadIdx.x;
    {
        int tot4 = (K * N) >> 2;
        const float4* W4 = (const float4*)W;
        float4* Wsh4 = (float4*)Wsh;
        for (int i = tid; i < tot4; i += blockDim.x) Wsh4[i] = W4[i];
    }
    __syncthreads();

    int warp = tid >> 5, lane = tid & 31;
    int c0 = lane * 4;
    bool active = lane < 25;

    for (int rbase = (blockIdx.x * 8 + warp) * 4; rbase < M; rbase += gridDim.x * 32) {
        u64 acc[4][PPL];
#pragma unroll
        for (int r = 0; r < 4; r++)
#pragma unroll
            for (int j = 0; j < PPL; j++) acc[r][j] = 0ull;

        int k0 = 0;
        for (; k0 + 32 <= K; k0 += 32) {
            float a[4];
#pragma unroll
            for (int r = 0; r < 4; r++) {
                int row = rbase + r;
                a[r] = (row < M) ? A[row * K + k0 + lane] : 0.f;
            }
#pragma unroll 8
            for (int t = 0; t < 32; t++) {
                u64 ad[4];
#pragma unroll
                for (int r = 0; r < 4; r++)
                    ad[r] = pack_dup(__shfl_sync(0xffffffffu, a[r], t));
                if (active) {
                    ulonglong2 wv = *(const ulonglong2*)&Wsh[(k0 + t) * N + c0];
#pragma unroll
                    for (int r = 0; r < 4; r++) {
                        ffma2(acc[r][0], ad[r], wv.x);
                        ffma2(acc[r][1], ad[r], wv.y);
                    }
                }
            }
        }
        if (k0 < K) {
            int rem = K - k0;
            float a[4];
#pragma unroll
            for (int r = 0; r < 4; r++) {
                int row = rbase + r;
                a[r] = (row < M && lane < rem) ? A[row * K + k0 + lane] : 0.f;
            }
            for (int t = 0; t < rem; t++) {
                u64 ad[4];
#pragma unroll
                for (int r = 0; r < 4; r++)
                    ad[r] = pack_dup(__shfl_sync(0xffffffffu, a[r], t));
                if (active) {
                    ulonglong2 wv = *(const ulonglong2*)&Wsh[(k0 + t) * N + c0];
#pragma unroll
                    for (int r = 0; r < 4; r++) {
                        ffma2(acc[r][0], ad[r], wv.x);
                        ffma2(acc[r][1], ad[r], wv.y);
                    }
                }
            }
        }

        if (active) {
#pragma unroll
            for (int r = 0; r < 4; r++) {
                int row = rbase + r;
                if (row < M) {
                    float so = sout[row];
                    float4 bv = *(const float4*)&bias[c0];
                    float2 p0 = unpack2(acc[r][0]);
                    float2 p1 = unpack2(acc[r][1]);
                    float4 v;
                    v.x = (p0.x + bv.x) * so;
                    v.y = (p0.y + bv.y) * so;
                    v.z = (p1.x + bv.z) * so;
                    v.w = (p1.y + bv.w) * so;
                    *(float4*)&Cout[row * N + c0] = v;
                }
            }
        }
    }
}

// ---------------- weight folding (all tiny) --------------------------------
// W12 = W1[100x100] @ W2[100x200]
__global__ void wprec1_kernel(const float* __restrict__ W1, const float* __restrict__ W2) {
    int idx = blockIdx.x * blockDim.x + threadIdx.x;
    if (idx >= LAT * H2) return;
    int i = idx / H2, j = idx % H2;
    float acc = 0.f;
    for (int k = 0; k < LAT; k++) acc += W1[i * LAT + k] * W2[k * H2 + j];
    g_W12[idx] = acc;
}
// Wfin = W12[100x200] @ Wc[200x55]
__global__ void wprec2_kernel(const float* __restrict__ Wc) {
    int idx = blockIdx.x * blockDim.x + threadIdx.x;
    if (idx >= LAT * NCLASS) return;
    int i = idx / NCLASS, j = idx % NCLASS;
    float acc = 0.f;
    for (int k = 0; k < H2; k++) acc += g_W12[i * H2 + k] * Wc[k * NCLASS + j];
    g_Wfin[idx] = acc;
}
// v1 = (b1 @ W2) @ Wc ; c0 = b2 @ Wc + bc
__global__ void wprec3_kernel(const float* __restrict__ b1, const float* __restrict__ W2,
                              const float* __restrict__ b2, const float* __restrict__ Wc,
                              const float* __restrict__ bc) {
    __shared__ float bw2[H2];
    int tid = threadIdx.x;
    for (int k = tid; k < H2; k += blockDim.x) {
        float acc = 0.f;
        for (int j = 0; j < LAT; j++) acc += b1[j] * W2[j * H2 + k];
        bw2[k] = acc;
    }
    __syncthreads();
    if (tid < NCLASS) {
        float v = 0.f, c = 0.f;
        for (int k = 0; k < H2; k++) {
            v += bw2[k] * Wc[k * NCLASS + tid];
            c += b2[k] * Wc[k * NCLASS + tid];
        }
        g_v1[tid] = v;
        g_c0[tid] = c + bc[tid];
    }
}

// ---------------- final: out[g,c] ------------------------------------------
__global__ void final_kernel(float* __restrict__ out) {
    __shared__ float px[LAT];
    __shared__ float spd;
    const float* poolX = g_zregion + ZR_POOLX;
    const float* poolD = g_zregion + ZR_POOLD;
    const float* cnt   = g_zregion + ZR_CNT;
    int g = blockIdx.x, tid = threadIdx.x;
    float invc = 1.0f / fmaxf(cnt[g], 1.0f);
    for (int i = tid; i < LAT; i += blockDim.x) px[i] = poolX[g * LAT + i] * invc;
    if (tid == 0) spd = poolD[g] * invc;
    __syncthreads();
    if (tid < NCLASS) {
        float acc = g_c0[tid] + spd * g_v1[tid];
        for (int k = 0; k < LAT; k++) acc += px[k] * g_Wfin[k * NCLASS + tid];
        out[g * NCLASS + tid] = acc;
    }
}

// ---------------- launch ---------------------------------------------------
extern "C" void kernel_launch(void* const* d_in, const int* in_sizes, int n_in,
                              void* d_out, int out_size) {
    const float* fsnet = (const float*)d_in[0];
    const int*   src   = (const int*)d_in[1];
    const int*   dst   = (const int*)d_in[2];
    const int*   gid   = (const int*)d_in[3];
    const float* W_ext = (const float*)d_in[4];
    const float* b_ext = (const float*)d_in[5];
    const float* W1    = (const float*)d_in[6];
    const float* b1    = (const float*)d_in[7];
    const float* W2    = (const float*)d_in[8];
    const float* b2    = (const float*)d_in[9];
    const float* Wc    = (const float*)d_in[10];
    const float* bc    = (const float*)d_in[11];
    float* out = (float*)d_out;

    int n   = in_sizes[3];
    int E   = in_sizes[1];
    int RAW = in_sizes[4] / LAT;

    float *bufA, *bufB, *inv_out, *inv_in, *s1, *zreg;
    cudaGetSymbolAddress((void**)&bufA,    g_bufA);
    cudaGetSymbolAddress((void**)&bufB,    g_bufB);
    cudaGetSymbolAddress((void**)&inv_out, g_inv_out);
    cudaGetSymbolAddress((void**)&inv_in,  g_inv_in);
    cudaGetSymbolAddress((void**)&s1,      g_s1);
    cudaGetSymbolAddress((void**)&zreg,    g_zregion);

    cudaFuncSetAttribute(gemm0_kernel,
                         cudaFuncAttributeMaxDynamicSharedMemorySize, RAW * LAT * 4);

    int nb = (n + 1023) / 1024;

    // 0. zero packed scratch (degree accums + pools + cnt)
    zero_kernel<<<148, 256>>>((float4*)zreg, ZR_TOTAL / 4);
    // 1. degree histograms
    degree_kernel<<<(E + 255) / 256, 256>>>(src, dst, E);
    // 2. per-chunk reduce + rsqrt factors + graph counts
    scanA_kernel<<<nb, 1024>>>(gid, n);
    // 3. GEMM0: bufA = (fsnet @ W_ext + b_ext) * inv_out      [profiled slot]
    gemm0_kernel<<<296, 256, RAW * LAT * 4>>>(fsnet, W_ext, b_ext, inv_out, bufA, n, RAW);
    // 4/5. finish CSR offsets
    scanB_kernel<<<1, 128>>>(nb, n);
    scanC_kernel<<<nb, 1024>>>(n);
    // 6. CSR scatter (by dst)
    scatter_kernel<<<(E + 255) / 256, 256>>>(src, dst, E);
    // 7-9. fold weights (independent of graph path)
    wprec1_kernel<<<(LAT * H2 + 255) / 256, 256>>>(W1, W2);
    wprec2_kernel<<<(LAT * NCLASS + 255) / 256, 256>>>(Wc);
    wprec3_kernel<<<1, 256>>>(b1, W2, b2, Wc, bc);
    // 10. prop1: bufB = P(x0) * inv_in * inv_out
    int pblocks = (n * 32 + 255) / 256;
    prop_csr_kernel<false><<<pblocks, 256>>>((const float4*)bufA, (float4*)bufB, s1, nullptr, n);
    // 11. prop2 fused with graph pooling: poolX += P(bufB) rows
    prop_csr_kernel<true><<<pblocks, 256>>>((const float4*)bufB, nullptr, inv_in, gid, n);
    // 12. d~ pooled by graph
    dtilde_kernel<<<pblocks, 256>>>(gid, n);
    // 13. out = (poolX/cnt) @ Wfin + (poolD/cnt) * v1 + c0
    final_kernel<<<NGRAPH, 128>>>(out);
}

// round 5
// speedup vs baseline: 1.4734x; 1.0350x over previous
#include <cuda_runtime.h>
#include <cstdint>

#define MAX_NODES 50000
#define LAT       100
#define NGRAPH    256
#define H2        200
#define NCLASS    55
#define MAX_EDGES 800000

typedef unsigned long long u64;

// ---------------- scratch (device globals) ---------------------------------
__device__ __align__(16) float g_bufA[MAX_NODES * LAT];   // x0 * inv_out
__device__ __align__(16) float g_bufB[MAX_NODES * LAT];   // P(x0) * inv_in * inv_out
__device__ __align__(16) float g_inv_out[MAX_NODES];
__device__ __align__(16) float g_inv_in[MAX_NODES];
__device__ __align__(16) float g_s1[MAX_NODES];           // inv_in * inv_out
__device__ __align__(16) int   g_off[MAX_NODES + 16];
__device__ __align__(16) int   g_cur[MAX_NODES];
__device__ __align__(16) int   g_csr[MAX_EDGES];
__device__ __align__(16) int   g_bsum[80];
__device__ __align__(16) int   g_bpre[80];
__device__ __align__(16) float g_W12[LAT * H2];           // W1 @ W2
__device__ __align__(16) float g_Wfin[LAT * NCLASS];      // W1 @ W2 @ Wc
__device__ __align__(16) float g_v1[64];                  // b1 @ W2 @ Wc
__device__ __align__(16) float g_c0[64];                  // b2 @ Wc + bc

// packed zero region: out_deg(f32) | deg_in(i32) | poolX | poolD | cnt
#define ZR_OUTDEG 0
#define ZR_DEGIN  50000
#define ZR_POOLX  100000
#define ZR_POOLD  125600
#define ZR_CNT    125856
#define ZR_TOTAL  126112
__device__ __align__(16) float g_zregion[ZR_TOTAL];

// ---------------- f32x2 packed math helpers --------------------------------
__device__ __forceinline__ void ffma2(u64& d, u64 a, u64 b) {
    asm("fma.rn.f32x2 %0, %1, %2, %0;" : "+l"(d) : "l"(a), "l"(b));
}
__device__ __forceinline__ float2 unpack2(u64 v) {
    float2 f; asm("mov.b64 {%0, %1}, %2;" : "=f"(f.x), "=f"(f.y) : "l"(v)); return f;
}

// ---------------- small kernels -------------------------------------------
__global__ void zero_kernel(float4* p, int n4) {
    int i = blockIdx.x * blockDim.x + threadIdx.x;
    float4 z = make_float4(0.f, 0.f, 0.f, 0.f);
    for (; i < n4; i += gridDim.x * blockDim.x) p[i] = z;
}

__global__ void degree_kernel(const int* __restrict__ src, const int* __restrict__ dst, int E) {
    float* out_deg = g_zregion + ZR_OUTDEG;
    int*   deg_in  = (int*)(g_zregion + ZR_DEGIN);
    int i = blockIdx.x * blockDim.x + threadIdx.x;
    if (i < E) {
        atomicAdd(&out_deg[src[i]], 1.0f);
        atomicAdd(&deg_in[dst[i]], 1);
    }
}

// scanA: per-chunk reduce of deg_in; also rsqrt factors + per-graph counts
__global__ void scanA_kernel(const int* __restrict__ gid, int n) {
    __shared__ int wsum[32];
    const float* out_deg = g_zregion + ZR_OUTDEG;
    const int*   deg_in  = (const int*)(g_zregion + ZR_DEGIN);
    float* cnt = g_zregion + ZR_CNT;
    int tid = threadIdx.x, lane = tid & 31, warp = tid >> 5;
    int i = blockIdx.x * 1024 + tid;
    int v = 0;
    if (i < n) {
        v = deg_in[i];
        float ii = rsqrtf(fmaxf((float)v, 1.0f));
        float io = rsqrtf(fmaxf(out_deg[i], 1.0f));
        g_inv_in[i]  = ii;
        g_inv_out[i] = io;
        g_s1[i]      = ii * io;
        atomicAdd(&cnt[gid[i]], 1.0f);
    }
    int s = v;
#pragma unroll
    for (int d = 16; d > 0; d >>= 1) s += __shfl_down_sync(0xffffffffu, s, d);
    if (lane == 0) wsum[warp] = s;
    __syncthreads();
    if (warp == 0) {
        int t = (lane < 32) ? wsum[lane] : 0;
#pragma unroll
        for (int d = 16; d > 0; d >>= 1) t += __shfl_down_sync(0xffffffffu, t, d);
        if (lane == 0) g_bsum[blockIdx.x] = t;
    }
}

// scanB: exclusive scan of block sums (tiny)
__global__ void scanB_kernel(int nb, int n) {
    __shared__ int s[80];
    int tid = threadIdx.x;
    if (tid < nb) s[tid] = g_bsum[tid];
    __syncthreads();
    if (tid == 0) {
        int run = 0;
        for (int b = 0; b < nb; b++) { int t = s[b]; s[b] = run; run += t; }
        g_off[n] = run;
    }
    __syncthreads();
    if (tid < nb) g_bpre[tid] = s[tid];
}

// scanC: local exclusive scan + block prefix -> off/cur
__global__ void scanC_kernel(int n) {
    __shared__ int wsum[32];
    const int* deg_in = (const int*)(g_zregion + ZR_DEGIN);
    int tid = threadIdx.x, lane = tid & 31, warp = tid >> 5;
    int i = blockIdx.x * 1024 + tid;
    int v = (i < n) ? deg_in[i] : 0;
    int s = v;
#pragma unroll
    for (int d = 1; d < 32; d <<= 1) {
        int t = __shfl_up_sync(0xffffffffu, s, d);
        if (lane >= d) s += t;
    }
    if (lane == 31) wsum[warp] = s;
    __syncthreads();
    if (warp == 0) {
        int ws = wsum[lane];
#pragma unroll
        for (int d = 1; d < 32; d <<= 1) {
            int t = __shfl_up_sync(0xffffffffu, ws, d);
            if (lane >= d) ws += t;
        }
        wsum[lane] = ws;
    }
    __syncthreads();
    int wpre = (warp > 0) ? wsum[warp - 1] : 0;
    int excl = s - v + wpre + g_bpre[blockIdx.x];
    if (i < n) { g_off[i] = excl; g_cur[i] = excl; }
}

__global__ void scatter_kernel(const int* __restrict__ src, const int* __restrict__ dst, int E) {
    int i = blockIdx.x * blockDim.x + threadIdx.x;
    if (i < E) {
        int p = atomicAdd(&g_cur[dst[i]], 1);
        g_csr[p] = src[i];
    }
}

// ---------------- CSR propagation -----------------------------------------
template <bool POOL>
__global__ void prop_csr_kernel(const float4* __restrict__ xs,
                                float4* __restrict__ agg,
                                const float* __restrict__ scale,
                                const int* __restrict__ gid, int n) {
    int node = (blockIdx.x * blockDim.x + threadIdx.x) >> 5;
    int lane = threadIdx.x & 31;
    if (node >= n) return;
    int b = g_off[node], e = g_off[node + 1];
    bool act = lane < 25;
    float4 a0 = make_float4(0.f, 0.f, 0.f, 0.f);
    float4 a1 = a0, a2 = a0, a3 = a0;
    unsigned base = (unsigned)lane;
    int k = b;
    for (; k + 4 <= e; k += 4) {
        int s0 = g_csr[k], s1 = g_csr[k + 1], s2 = g_csr[k + 2], s3 = g_csr[k + 3];
        if (act) {
            float4 v0 = xs[(unsigned)s0 * 25u + base];
            float4 v1 = xs[(unsigned)s1 * 25u + base];
            float4 v2 = xs[(unsigned)s2 * 25u + base];
            float4 v3 = xs[(unsigned)s3 * 25u + base];
            a0.x += v0.x; a0.y += v0.y; a0.z += v0.z; a0.w += v0.w;
            a1.x += v1.x; a1.y += v1.y; a1.z += v1.z; a1.w += v1.w;
            a2.x += v2.x; a2.y += v2.y; a2.z += v2.z; a2.w += v2.w;
            a3.x += v3.x; a3.y += v3.y; a3.z += v3.z; a3.w += v3.w;
        }
    }
    for (; k < e; k++) {
        int s0 = g_csr[k];
        if (act) {
            float4 v0 = xs[(unsigned)s0 * 25u + base];
            a0.x += v0.x; a0.y += v0.y; a0.z += v0.z; a0.w += v0.w;
        }
    }
    if (act) {
        float sc = scale[node];
        float x = (a0.x + a1.x + a2.x + a3.x) * sc;
        float y = (a0.y + a1.y + a2.y + a3.y) * sc;
        float z = (a0.z + a1.z + a2.z + a3.z) * sc;
        float w = (a0.w + a1.w + a2.w + a3.w) * sc;
        if (!POOL) {
            agg[(unsigned)node * 25u + base] = make_float4(x, y, z, w);
        } else {
            float* poolX = g_zregion + ZR_POOLX;
            float* p = poolX + (unsigned)gid[node] * 100u + base * 4u;
            asm volatile("red.global.add.v4.f32 [%0], {%1,%2,%3,%4};"
                         :: "l"(p), "f"(x), "f"(y), "f"(z), "f"(w)
                         : "memory");
        }
    }
}

// ---------------- d~ = P(ones), pooled by graph ----------------------------
__global__ void dtilde_kernel(const int* __restrict__ gid, int n) {
    int node = (blockIdx.x * blockDim.x + threadIdx.x) >> 5;
    int lane = threadIdx.x & 31;
    if (node >= n) return;
    int b = g_off[node], e = g_off[node + 1];
    float s = 0.f;
    for (int k = b + lane; k < e; k += 32) s += g_inv_out[g_csr[k]];
#pragma unroll
    for (int d = 16; d > 0; d >>= 1) s += __shfl_down_sync(0xffffffffu, s, d);
    if (lane == 0) {
        float* poolD = g_zregion + ZR_POOLD;
        atomicAdd(&poolD[gid[node]], s * g_inv_in[node]);
    }
}

// ---------------- GEMM0: C = (A @ W + b) .* sout ---------------------------
// Register-tiled SGEMM: block tile M=80 x N=100, K-chunk 32.
// 250 workers of 256 threads; each computes 8 rows x 4 cols via f32x2:
//   As staged transposed [k][m]  -> ulonglong2 LDS = packed row-pairs (no movs)
//   Ws staged duplicated [k][2c] -> ulonglong2 LDS = dup'd col operands (no movs)
// Inner loop per k: 4x LDS.128 + 16x FFMA2.
#define TM 80
#define KC 32
__global__ void __launch_bounds__(256) gemm0_kernel(
        const float* __restrict__ A,
        const float* __restrict__ W,
        const float* __restrict__ bias,
        const float* __restrict__ sout,
        float* __restrict__ C, int M, int K) {
    __shared__ float As[KC][84];     // transposed A chunk (+pad)
    __shared__ float Ws2[KC][200];   // duplicated W chunk

    int tid = threadIdx.x;
    int m0 = blockIdx.x * TM;
    bool worker = tid < 250;
    int ty = tid / 25;               // 0..9 (workers)
    int tx = tid - ty * 25;          // 0..24
    int r0 = ty * 8;                 // row offset in tile
    int c0 = tx * 4;                 // col offset

    u64 acc[4][4];
#pragma unroll
    for (int p = 0; p < 4; p++)
#pragma unroll
        for (int c = 0; c < 4; c++) acc[p][c] = 0ull;

    int nk = (K + KC - 1) / KC;

    // staging registers for prefetch
    float a_st[3][4];
    float w_st[4][4];
    int   a_row[3], a_kq[3];
    int   w_k[4], w_c4[4];

    // decode static load assignments
#pragma unroll
    for (int s = 0; s < 3; s++) {
        int idx = tid + s * 256;
        a_row[s] = idx >> 3;         // 0..79
        a_kq[s]  = idx & 7;          // float4 index within 32 k
    }
#pragma unroll
    for (int s = 0; s < 4; s++) {
        int idx = tid + s * 256;
        w_k[s]  = idx / 25;          // 0..31
        w_c4[s] = idx - w_k[s] * 25; // 0..24
    }

    // ---- load chunk 0 into regs ----
    {
        int k0 = 0;
#pragma unroll
        for (int s = 0; s < 3; s++) {
            int idx = tid + s * 256;
            if (idx < 640) {
                int gr = m0 + a_row[s]; if (gr >= M) gr = M - 1;
                int gk = k0 + a_kq[s] * 4;
#pragma unroll
                for (int j = 0; j < 4; j++)
                    a_st[s][j] = (gk + j < K) ? A[(size_t)gr * K + gk + j] : 0.f;
            }
        }
#pragma unroll
        for (int s = 0; s < 4; s++) {
            int idx = tid + s * 256;
            if (idx < 800) {
                int gk = k0 + w_k[s];
                int gc = w_c4[s] * 4;
                if (gk < K) {
                    float4 wv = *(const float4*)&W[(size_t)gk * LAT + gc];
                    w_st[s][0] = wv.x; w_st[s][1] = wv.y; w_st[s][2] = wv.z; w_st[s][3] = wv.w;
                } else {
                    w_st[s][0] = w_st[s][1] = w_st[s][2] = w_st[s][3] = 0.f;
                }
            }
        }
    }

    for (int ch = 0; ch < nk; ch++) {
        __syncthreads();   // smem free (previous compute done)
        // regs -> smem
#pragma unroll
        for (int s = 0; s < 3; s++) {
            int idx = tid + s * 256;
            if (idx < 640) {
                int kb = a_kq[s] * 4, row = a_row[s];
#pragma unroll
                for (int j = 0; j < 4; j++) As[kb + j][row] = a_st[s][j];
            }
        }
#pragma unroll
        for (int s = 0; s < 4; s++) {
            int idx = tid + s * 256;
            if (idx < 800) {
                int kk = w_k[s], cc = w_c4[s] * 8;
                float4 lo = make_float4(w_st[s][0], w_st[s][0], w_st[s][1], w_st[s][1]);
                float4 hi = make_float4(w_st[s][2], w_st[s][2], w_st[s][3], w_st[s][3]);
                *(float4*)&Ws2[kk][cc]     = lo;
                *(float4*)&Ws2[kk][cc + 4] = hi;
            }
        }
        // prefetch next chunk
        if (ch + 1 < nk) {
            int k0 = (ch + 1) * KC;
#pragma unroll
            for (int s = 0; s < 3; s++) {
                int idx = tid + s * 256;
                if (idx < 640) {
                    int gr = m0 + a_row[s]; if (gr >= M) gr = M - 1;
                    int gk = k0 + a_kq[s] * 4;
#pragma unroll
                    for (int j = 0; j < 4; j++)
                        a_st[s][j] = (gk + j < K) ? A[(size_t)gr * K + gk + j] : 0.f;
                }
            }
#pragma unroll
            for (int s = 0; s < 4; s++) {
                int idx = tid + s * 256;
                if (idx < 800) {
                    int gk = k0 + w_k[s];
                    int gc = w_c4[s] * 4;
                    if (gk < K) {
                        float4 wv = *(const float4*)&W[(size_t)gk * LAT + gc];
                        w_st[s][0] = wv.x; w_st[s][1] = wv.y; w_st[s][2] = wv.z; w_st[s][3] = wv.w;
                    } else {
                        w_st[s][0] = w_st[s][1] = w_st[s][2] = w_st[s][3] = 0.f;
                    }
                }
            }
        }
        __syncthreads();   // smem ready
        if (worker) {
#pragma unroll 8
            for (int k = 0; k < KC; k++) {
                ulonglong2 av0 = *(const ulonglong2*)&As[k][r0];
                ulonglong2 av1 = *(const ulonglong2*)&As[k][r0 + 4];
                ulonglong2 wv0 = *(const ulonglong2*)&Ws2[k][c0 * 2];
                ulonglong2 wv1 = *(const ulonglong2*)&Ws2[k][c0 * 2 + 4];
                ffma2(acc[0][0], av0.x, wv0.x); ffma2(acc[0][1], av0.x, wv0.y);
                ffma2(acc[0][2], av0.x, wv1.x); ffma2(acc[0][3], av0.x, wv1.y);
                ffma2(acc[1][0], av0.y, wv0.x); ffma2(acc[1][1], av0.y, wv0.y);
                ffma2(acc[1][2], av0.y, wv1.x); ffma2(acc[1][3], av0.y, wv1.y);
                ffma2(acc[2][0], av1.x, wv0.x); ffma2(acc[2][1], av1.x, wv0.y);
                ffma2(acc[2][2], av1.x, wv1.x); ffma2(acc[2][3], av1.x, wv1.y);
                ffma2(acc[3][0], av1.y, wv0.x); ffma2(acc[3][1], av1.y, wv0.y);
                ffma2(acc[3][2], av1.y, wv1.x); ffma2(acc[3][3], av1.y, wv1.y);
            }
        }
    }

    if (worker) {
        float4 bv = *(const float4*)&bias[c0];
#pragma unroll
        for (int p = 0; p < 4; p++) {
            float2 v0 = unpack2(acc[p][0]);
            float2 v1 = unpack2(acc[p][1]);
            float2 v2 = unpack2(acc[p][2]);
            float2 v3 = unpack2(acc[p][3]);
            int row = m0 + r0 + 2 * p;
            if (row < M) {
                float so = sout[row];
                float4 v = make_float4((v0.x + bv.x) * so, (v1.x + bv.y) * so,
                                       (v2.x + bv.z) * so, (v3.x + bv.w) * so);
                *(float4*)&C[(size_t)row * LAT + c0] = v;
            }
            if (row + 1 < M) {
                float so = sout[row + 1];
                float4 v = make_float4((v0.y + bv.x) * so, (v1.y + bv.y) * so,
                                       (v2.y + bv.z) * so, (v3.y + bv.w) * so);
                *(float4*)&C[(size_t)(row + 1) * LAT + c0] = v;
            }
        }
    }
}

// ---------------- weight folding (all tiny) --------------------------------
__global__ void wprec1_kernel(const float* __restrict__ W1, const float* __restrict__ W2) {
    int idx = blockIdx.x * blockDim.x + threadIdx.x;
    if (idx >= LAT * H2) return;
    int i = idx / H2, j = idx % H2;
    float acc = 0.f;
    for (int k = 0; k < LAT; k++) acc += W1[i * LAT + k] * W2[k * H2 + j];
    g_W12[idx] = acc;
}
__global__ void wprec2_kernel(const float* __restrict__ Wc) {
    int idx = blockIdx.x * blockDim.x + threadIdx.x;
    if (idx >= LAT * NCLASS) return;
    int i = idx / NCLASS, j = idx % NCLASS;
    float acc = 0.f;
    for (int k = 0; k < H2; k++) acc += g_W12[i * H2 + k] * Wc[k * NCLASS + j];
    g_Wfin[idx] = acc;
}
__global__ void wprec3_kernel(const float* __restrict__ b1, const float* __restrict__ W2,
                              const float* __restrict__ b2, const float* __restrict__ Wc,
                              const float* __restrict__ bc) {
    __shared__ float bw2[H2];
    int tid = threadIdx.x;
    for (int k = tid; k < H2; k += blockDim.x) {
        float acc = 0.f;
        for (int j = 0; j < LAT; j++) acc += b1[j] * W2[j * H2 + k];
        bw2[k] = acc;
    }
    __syncthreads();
    if (tid < NCLASS) {
        float v = 0.f, c = 0.f;
        for (int k = 0; k < H2; k++) {
            v += bw2[k] * Wc[k * NCLASS + tid];
            c += b2[k] * Wc[k * NCLASS + tid];
        }
        g_v1[tid] = v;
        g_c0[tid] = c + bc[tid];
    }
}

// ---------------- final: out[g,c] ------------------------------------------
__global__ void final_kernel(float* __restrict__ out) {
    __shared__ float px[LAT];
    __shared__ float spd;
    const float* poolX = g_zregion + ZR_POOLX;
    const float* poolD = g_zregion + ZR_POOLD;
    const float* cnt   = g_zregion + ZR_CNT;
    int g = blockIdx.x, tid = threadIdx.x;
    float invc = 1.0f / fmaxf(cnt[g], 1.0f);
    for (int i = tid; i < LAT; i += blockDim.x) px[i] = poolX[g * LAT + i] * invc;
    if (tid == 0) spd = poolD[g] * invc;
    __syncthreads();
    if (tid < NCLASS) {
        float acc = g_c0[tid] + spd * g_v1[tid];
        for (int k = 0; k < LAT; k++) acc += px[k] * g_Wfin[k * NCLASS + tid];
        out[g * NCLASS + tid] = acc;
    }
}

// ---------------- launch ---------------------------------------------------
extern "C" void kernel_launch(void* const* d_in, const int* in_sizes, int n_in,
                              void* d_out, int out_size) {
    const float* fsnet = (const float*)d_in[0];
    const int*   src   = (const int*)d_in[1];
    const int*   dst   = (const int*)d_in[2];
    const int*   gid   = (const int*)d_in[3];
    const float* W_ext = (const float*)d_in[4];
    const float* b_ext = (const float*)d_in[5];
    const float* W1    = (const float*)d_in[6];
    const float* b1    = (const float*)d_in[7];
    const float* W2    = (const float*)d_in[8];
    const float* b2    = (const float*)d_in[9];
    const float* Wc    = (const float*)d_in[10];
    const float* bc    = (const float*)d_in[11];
    float* out = (float*)d_out;

    int n   = in_sizes[3];
    int E   = in_sizes[1];
    int RAW = in_sizes[4] / LAT;

    float *bufA, *bufB, *inv_out, *inv_in, *s1, *zreg;
    cudaGetSymbolAddress((void**)&bufA,    g_bufA);
    cudaGetSymbolAddress((void**)&bufB,    g_bufB);
    cudaGetSymbolAddress((void**)&inv_out, g_inv_out);
    cudaGetSymbolAddress((void**)&inv_in,  g_inv_in);
    cudaGetSymbolAddress((void**)&s1,      g_s1);
    cudaGetSymbolAddress((void**)&zreg,    g_zregion);

    int nb = (n + 1023) / 1024;

    // 0. zero packed scratch
    zero_kernel<<<148, 256>>>((float4*)zreg, ZR_TOTAL / 4);
    // 1. degree histograms
    degree_kernel<<<(E + 255) / 256, 256>>>(src, dst, E);
    // 2. per-chunk reduce + rsqrt factors + graph counts
    scanA_kernel<<<nb, 1024>>>(gid, n);
    // 3. GEMM0 (profiled slot): bufA = (fsnet @ W_ext + b_ext) * inv_out
    gemm0_kernel<<<(n + TM - 1) / TM, 256>>>(fsnet, W_ext, b_ext, inv_out, bufA, n, RAW);
    // 4/5. finish CSR offsets
    scanB_kernel<<<1, 128>>>(nb, n);
    scanC_kernel<<<nb, 1024>>>(n);
    // 6. CSR scatter (by dst)
    scatter_kernel<<<(E + 255) / 256, 256>>>(src, dst, E);
    // 7-9. fold weights
    wprec1_kernel<<<(LAT * H2 + 255) / 256, 256>>>(W1, W2);
    wprec2_kernel<<<(LAT * NCLASS + 255) / 256, 256>>>(Wc);
    wprec3_kernel<<<1, 256>>>(b1, W2, b2, Wc, bc);
    // 10. prop1: bufB = P(x0) * inv_in * inv_out
    int pblocks = (n * 32 + 255) / 256;
    prop_csr_kernel<false><<<pblocks, 256>>>((const float4*)bufA, (float4*)bufB, s1, nullptr, n);
    // 11. prop2 fused with graph pooling
    prop_csr_kernel<true><<<pblocks, 256>>>((const float4*)bufB, nullptr, inv_in, gid, n);
    // 12. d~ pooled by graph
    dtilde_kernel<<<pblocks, 256>>>(gid, n);
    // 13. out = (poolX/cnt) @ Wfin + (poolD/cnt) * v1 + c0
    final_kernel<<<NGRAPH, 128>>>(out);
}

// round 6
// speedup vs baseline: 1.6982x; 1.1525x over previous
#include <cuda_runtime.h>
#include <cstdint>

#define MAX_NODES 50000
#define LAT       100
#define NGRAPH    256
#define H2        200
#define NCLASS    55
#define MAX_EDGES 800000

typedef unsigned long long u64;

// ---------------- scratch (device globals) ---------------------------------
__device__ __align__(16) float g_bufA[MAX_NODES * LAT];   // x0 * inv_out
__device__ __align__(16) float g_bufB[MAX_NODES * LAT];   // P(x0) * inv_in * inv_out
__device__ __align__(16) float g_inv_out[MAX_NODES];
__device__ __align__(16) float g_inv_in[MAX_NODES];
__device__ __align__(16) float g_s1[MAX_NODES];           // inv_in * inv_out
__device__ __align__(16) int   g_off[MAX_NODES + 16];
__device__ __align__(16) int   g_cur[MAX_NODES];
__device__ __align__(16) int   g_csr[MAX_EDGES];
__device__ __align__(16) int   g_bsum[80];
__device__ __align__(16) int   g_bpre[80];
__device__ __align__(16) float g_W12[LAT * H2];           // W1 @ W2
__device__ __align__(16) float g_Wfin[LAT * NCLASS];      // W1 @ W2 @ Wc
__device__ __align__(16) float g_v1[64];                  // b1 @ W2 @ Wc
__device__ __align__(16) float g_c0[64];                  // b2 @ Wc + bc

// packed zero region: out_deg(f32) | deg_in(i32) | poolX | poolD | cnt
#define ZR_OUTDEG 0
#define ZR_DEGIN  50000
#define ZR_POOLX  100000
#define ZR_POOLD  125600
#define ZR_CNT    125856
#define ZR_TOTAL  126112
__device__ __align__(16) float g_zregion[ZR_TOTAL];

// ---------------- f32x2 packed math helpers --------------------------------
__device__ __forceinline__ void ffma2(u64& d, u64 a, u64 b) {
    asm("fma.rn.f32x2 %0, %1, %2, %0;" : "+l"(d) : "l"(a), "l"(b));
}
__device__ __forceinline__ float2 unpack2(u64 v) {
    float2 f; asm("mov.b64 {%0, %1}, %2;" : "=f"(f.x), "=f"(f.y) : "l"(v)); return f;
}
__device__ __forceinline__ u64 swap2(u64 v) {
    float2 f = unpack2(v);
    u64 r; asm("mov.b64 %0, {%1, %2};" : "=l"(r) : "f"(f.y), "f"(f.x));
    return r;
}

// ---------------- small kernels -------------------------------------------
__global__ void zero_kernel(float4* p, int n4) {
    int i = blockIdx.x * blockDim.x + threadIdx.x;
    float4 z = make_float4(0.f, 0.f, 0.f, 0.f);
    for (; i < n4; i += gridDim.x * blockDim.x) p[i] = z;
}

__global__ void degree_kernel(const int* __restrict__ src, const int* __restrict__ dst, int E) {
    float* out_deg = g_zregion + ZR_OUTDEG;
    int*   deg_in  = (int*)(g_zregion + ZR_DEGIN);
    int i = blockIdx.x * blockDim.x + threadIdx.x;
    if (i < E) {
        atomicAdd(&out_deg[src[i]], 1.0f);
        atomicAdd(&deg_in[dst[i]], 1);
    }
}

// scanA: per-chunk reduce of deg_in; also rsqrt factors + per-graph counts
__global__ void scanA_kernel(const int* __restrict__ gid, int n) {
    __shared__ int wsum[32];
    const float* out_deg = g_zregion + ZR_OUTDEG;
    const int*   deg_in  = (const int*)(g_zregion + ZR_DEGIN);
    float* cnt = g_zregion + ZR_CNT;
    int tid = threadIdx.x, lane = tid & 31, warp = tid >> 5;
    int i = blockIdx.x * 1024 + tid;
    int v = 0;
    if (i < n) {
        v = deg_in[i];
        float ii = rsqrtf(fmaxf((float)v, 1.0f));
        float io = rsqrtf(fmaxf(out_deg[i], 1.0f));
        g_inv_in[i]  = ii;
        g_inv_out[i] = io;
        g_s1[i]      = ii * io;
        atomicAdd(&cnt[gid[i]], 1.0f);
    }
    int s = v;
#pragma unroll
    for (int d = 16; d > 0; d >>= 1) s += __shfl_down_sync(0xffffffffu, s, d);
    if (lane == 0) wsum[warp] = s;
    __syncthreads();
    if (warp == 0) {
        int t = (lane < 32) ? wsum[lane] : 0;
#pragma unroll
        for (int d = 16; d > 0; d >>= 1) t += __shfl_down_sync(0xffffffffu, t, d);
        if (lane == 0) g_bsum[blockIdx.x] = t;
    }
}

// scanB: exclusive scan of block sums (tiny)
__global__ void scanB_kernel(int nb, int n) {
    __shared__ int s[80];
    int tid = threadIdx.x;
    if (tid < nb) s[tid] = g_bsum[tid];
    __syncthreads();
    if (tid == 0) {
        int run = 0;
        for (int b = 0; b < nb; b++) { int t = s[b]; s[b] = run; run += t; }
        g_off[n] = run;
    }
    __syncthreads();
    if (tid < nb) g_bpre[tid] = s[tid];
}

// scanC: local exclusive scan + block prefix -> off/cur
__global__ void scanC_kernel(int n) {
    __shared__ int wsum[32];
    const int* deg_in = (const int*)(g_zregion + ZR_DEGIN);
    int tid = threadIdx.x, lane = tid & 31, warp = tid >> 5;
    int i = blockIdx.x * 1024 + tid;
    int v = (i < n) ? deg_in[i] : 0;
    int s = v;
#pragma unroll
    for (int d = 1; d < 32; d <<= 1) {
        int t = __shfl_up_sync(0xffffffffu, s, d);
        if (lane >= d) s += t;
    }
    if (lane == 31) wsum[warp] = s;
    __syncthreads();
    if (warp == 0) {
        int ws = wsum[lane];
#pragma unroll
        for (int d = 1; d < 32; d <<= 1) {
            int t = __shfl_up_sync(0xffffffffu, ws, d);
            if (lane >= d) ws += t;
        }
        wsum[lane] = ws;
    }
    __syncthreads();
    int wpre = (warp > 0) ? wsum[warp - 1] : 0;
    int excl = s - v + wpre + g_bpre[blockIdx.x];
    if (i < n) { g_off[i] = excl; g_cur[i] = excl; }
}

__global__ void scatter_kernel(const int* __restrict__ src, const int* __restrict__ dst, int E) {
    int i = blockIdx.x * blockDim.x + threadIdx.x;
    if (i < E) {
        int p = atomicAdd(&g_cur[dst[i]], 1);
        g_csr[p] = src[i];
    }
}

// ---------------- CSR propagation -----------------------------------------
template <bool POOL>
__global__ void prop_csr_kernel(const float4* __restrict__ xs,
                                float4* __restrict__ agg,
                                const float* __restrict__ scale,
                                const int* __restrict__ gid, int n) {
    int node = (blockIdx.x * blockDim.x + threadIdx.x) >> 5;
    int lane = threadIdx.x & 31;
    if (node >= n) return;
    int b = g_off[node], e = g_off[node + 1];
    bool act = lane < 25;
    float4 a0 = make_float4(0.f, 0.f, 0.f, 0.f);
    float4 a1 = a0, a2 = a0, a3 = a0;
    unsigned base = (unsigned)lane;
    int k = b;
    for (; k + 4 <= e; k += 4) {
        int s0 = g_csr[k], s1 = g_csr[k + 1], s2 = g_csr[k + 2], s3 = g_csr[k + 3];
        if (act) {
            float4 v0 = xs[(unsigned)s0 * 25u + base];
            float4 v1 = xs[(unsigned)s1 * 25u + base];
            float4 v2 = xs[(unsigned)s2 * 25u + base];
            float4 v3 = xs[(unsigned)s3 * 25u + base];
            a0.x += v0.x; a0.y += v0.y; a0.z += v0.z; a0.w += v0.w;
            a1.x += v1.x; a1.y += v1.y; a1.z += v1.z; a1.w += v1.w;
            a2.x += v2.x; a2.y += v2.y; a2.z += v2.z; a2.w += v2.w;
            a3.x += v3.x; a3.y += v3.y; a3.z += v3.z; a3.w += v3.w;
        }
    }
    for (; k < e; k++) {
        int s0 = g_csr[k];
        if (act) {
            float4 v0 = xs[(unsigned)s0 * 25u + base];
            a0.x += v0.x; a0.y += v0.y; a0.z += v0.z; a0.w += v0.w;
        }
    }
    if (act) {
        float sc = scale[node];
        float x = (a0.x + a1.x + a2.x + a3.x) * sc;
        float y = (a0.y + a1.y + a2.y + a3.y) * sc;
        float z = (a0.z + a1.z + a2.z + a3.z) * sc;
        float w = (a0.w + a1.w + a2.w + a3.w) * sc;
        if (!POOL) {
            agg[(unsigned)node * 25u + base] = make_float4(x, y, z, w);
        } else {
            float* poolX = g_zregion + ZR_POOLX;
            float* p = poolX + (unsigned)gid[node] * 100u + base * 4u;
            asm volatile("red.global.add.v4.f32 [%0], {%1,%2,%3,%4};"
                         :: "l"(p), "f"(x), "f"(y), "f"(z), "f"(w)
                         : "memory");
        }
    }
}

// ---------------- d~ = P(ones), pooled by graph ----------------------------
__global__ void dtilde_kernel(const int* __restrict__ gid, int n) {
    int node = (blockIdx.x * blockDim.x + threadIdx.x) >> 5;
    int lane = threadIdx.x & 31;
    if (node >= n) return;
    int b = g_off[node], e = g_off[node + 1];
    float s = 0.f;
    for (int k = b + lane; k < e; k += 32) s += g_inv_out[g_csr[k]];
#pragma unroll
    for (int d = 16; d > 0; d >>= 1) s += __shfl_down_sync(0xffffffffu, s, d);
    if (lane == 0) {
        float* poolD = g_zregion + ZR_POOLD;
        atomicAdd(&poolD[gid[node]], s * g_inv_in[node]);
    }
}

// ---------------- GEMM0: C = (A @ W + b) .* sout ---------------------------
// Block tile 160 rows x 100 cols, K-chunk 32. 250 workers of 256 threads,
// each computes 16 rows x 4 cols.
//   As[k][m] natural (row-pairs packed for f32x2): 4x LDS.128/k, ty-only
//            addresses -> broadcast (~1 wavefront each)
//   Ws[k][c] natural: 1x LDS.128/k gives both col-pairs, contiguous 400B ->
//            conflict-free; anti-diagonal via 2 register swaps (ALU pipe)
// Per k per thread: 5 LDS + 4 mov + 32 FFMA2 (64 FMAs).
#define TM 160
#define KC 32
#define SA 164
#define SW 104
__global__ void __launch_bounds__(256, 2) gemm0_kernel(
        const float* __restrict__ A,
        const float* __restrict__ W,
        const float* __restrict__ bias,
        const float* __restrict__ sout,
        float* __restrict__ C, int M, int K) {
    __shared__ float As[KC][SA];
    __shared__ float Ws[KC][SW];

    int tid = threadIdx.x;
    int m0 = blockIdx.x * TM;
    bool worker = tid < 250;
    int ty = tid / 25;               // 0..9 for workers
    int tx = tid - ty * 25;          // 0..24
    int r0 = ty * 16;
    int c0 = tx * 4;

    u64 accd[8][2], accx[8][2];
#pragma unroll
    for (int p = 0; p < 8; p++) {
        accd[p][0] = accd[p][1] = 0ull;
        accx[p][0] = accx[p][1] = 0ull;
    }

    int nk = (K + KC - 1) / KC;
    for (int ch = 0; ch < nk; ch++) {
        int k0 = ch * KC;
        __syncthreads();
        // stage A transposed: As[k][m]
#pragma unroll
        for (int s = 0; s < 5; s++) {
            int idx = tid + s * 256;             // < 1280
            int row = idx >> 3;
            int q = idx & 7;
            int gr = m0 + row; if (gr >= M) gr = M - 1;
            int gk = k0 + q * 4;
            float4 v;
            if (gk + 3 < K) {
                v = *(const float4*)&A[(size_t)gr * K + gk];
            } else {
                v.x = (gk     < K) ? A[(size_t)gr * K + gk]     : 0.f;
                v.y = (gk + 1 < K) ? A[(size_t)gr * K + gk + 1] : 0.f;
                v.z = (gk + 2 < K) ? A[(size_t)gr * K + gk + 2] : 0.f;
                v.w = (gk + 3 < K) ? A[(size_t)gr * K + gk + 3] : 0.f;
            }
            As[q * 4 + 0][row] = v.x;
            As[q * 4 + 1][row] = v.y;
            As[q * 4 + 2][row] = v.z;
            As[q * 4 + 3][row] = v.w;
        }
        // stage W natural: Ws[k][c]
#pragma unroll
        for (int s = 0; s < 4; s++) {
            int idx = tid + s * 256;
            if (idx < 800) {
                int kk = idx / 25;
                int c4 = idx - kk * 25;
                int gk = k0 + kk;
                float4 wv = (gk < K) ? *(const float4*)&W[(size_t)gk * LAT + c4 * 4]
                                     : make_float4(0.f, 0.f, 0.f, 0.f);
                *(float4*)&Ws[kk][c4 * 4] = wv;
            }
        }
        __syncthreads();
        if (worker) {
#pragma unroll 4
            for (int k = 0; k < KC; k++) {
                ulonglong2 a01 = *(const ulonglong2*)&As[k][r0];
                ulonglong2 a23 = *(const ulonglong2*)&As[k][r0 + 4];
                ulonglong2 a45 = *(const ulonglong2*)&As[k][r0 + 8];
                ulonglong2 a67 = *(const ulonglong2*)&As[k][r0 + 12];
                ulonglong2 w  = *(const ulonglong2*)&Ws[k][c0];
                u64 wxs = swap2(w.x);
                u64 wys = swap2(w.y);
                ffma2(accd[0][0], a01.x, w.x);  ffma2(accx[0][0], a01.x, wxs);
                ffma2(accd[0][1], a01.x, w.y);  ffma2(accx[0][1], a01.x, wys);
                ffma2(accd[1][0], a01.y, w.x);  ffma2(accx[1][0], a01.y, wxs);
                ffma2(accd[1][1], a01.y, w.y);  ffma2(accx[1][1], a01.y, wys);
                ffma2(accd[2][0], a23.x, w.x);  ffma2(accx[2][0], a23.x, wxs);
                ffma2(accd[2][1], a23.x, w.y);  ffma2(accx[2][1], a23.x, wys);
                ffma2(accd[3][0], a23.y, w.x);  ffma2(accx[3][0], a23.y, wxs);
                ffma2(accd[3][1], a23.y, w.y);  ffma2(accx[3][1], a23.y, wys);
                ffma2(accd[4][0], a45.x, w.x);  ffma2(accx[4][0], a45.x, wxs);
                ffma2(accd[4][1], a45.x, w.y);  ffma2(accx[4][1], a45.x, wys);
                ffma2(accd[5][0], a45.y, w.x);  ffma2(accx[5][0], a45.y, wxs);
                ffma2(accd[5][1], a45.y, w.y);  ffma2(accx[5][1], a45.y, wys);
                ffma2(accd[6][0], a67.x, w.x);  ffma2(accx[6][0], a67.x, wxs);
                ffma2(accd[6][1], a67.x, w.y);  ffma2(accx[6][1], a67.x, wys);
                ffma2(accd[7][0], a67.y, w.x);  ffma2(accx[7][0], a67.y, wxs);
                ffma2(accd[7][1], a67.y, w.y);  ffma2(accx[7][1], a67.y, wys);
            }
        }
    }

    if (worker) {
        float4 bv = *(const float4*)&bias[c0];
#pragma unroll
        for (int p = 0; p < 8; p++) {
            float2 d0 = unpack2(accd[p][0]);
            float2 x0 = unpack2(accx[p][0]);
            float2 d1 = unpack2(accd[p][1]);
            float2 x1 = unpack2(accx[p][1]);
            int row = m0 + r0 + 2 * p;
            if (row < M) {
                float so = sout[row];
                float4 v = make_float4((d0.x + bv.x) * so, (x0.x + bv.y) * so,
                                       (d1.x + bv.z) * so, (x1.x + bv.w) * so);
                *(float4*)&C[(size_t)row * LAT + c0] = v;
            }
            if (row + 1 < M) {
                float so = sout[row + 1];
                float4 v = make_float4((x0.y + bv.x) * so, (d0.y + bv.y) * so,
                                       (x1.y + bv.z) * so, (d1.y + bv.w) * so);
                *(float4*)&C[(size_t)(row + 1) * LAT + c0] = v;
            }
        }
    }
}

// ---------------- weight folding (all tiny) --------------------------------
__global__ void wprec1_kernel(const float* __restrict__ W1, const float* __restrict__ W2) {
    int idx = blockIdx.x * blockDim.x + threadIdx.x;
    if (idx >= LAT * H2) return;
    int i = idx / H2, j = idx % H2;
    float acc = 0.f;
    for (int k = 0; k < LAT; k++) acc += W1[i * LAT + k] * W2[k * H2 + j];
    g_W12[idx] = acc;
}
__global__ void wprec2_kernel(const float* __restrict__ Wc) {
    int idx = blockIdx.x * blockDim.x + threadIdx.x;
    if (idx >= LAT * NCLASS) return;
    int i = idx / NCLASS, j = idx % NCLASS;
    float acc = 0.f;
    for (int k = 0; k < H2; k++) acc += g_W12[i * H2 + k] * Wc[k * NCLASS + j];
    g_Wfin[idx] = acc;
}
__global__ void wprec3_kernel(const float* __restrict__ b1, const float* __restrict__ W2,
                              const float* __restrict__ b2, const float* __restrict__ Wc,
                              const float* __restrict__ bc) {
    __shared__ float bw2[H2];
    int tid = threadIdx.x;
    for (int k = tid; k < H2; k += blockDim.x) {
        float acc = 0.f;
        for (int j = 0; j < LAT; j++) acc += b1[j] * W2[j * H2 + k];
        bw2[k] = acc;
    }
    __syncthreads();
    if (tid < NCLASS) {
        float v = 0.f, c = 0.f;
        for (int k = 0; k < H2; k++) {
            v += bw2[k] * Wc[k * NCLASS + tid];
            c += b2[k] * Wc[k * NCLASS + tid];
        }
        g_v1[tid] = v;
        g_c0[tid] = c + bc[tid];
    }
}

// ---------------- final: out[g,c] ------------------------------------------
__global__ void final_kernel(float* __restrict__ out) {
    __shared__ float px[LAT];
    __shared__ float spd;
    const float* poolX = g_zregion + ZR_POOLX;
    const float* poolD = g_zregion + ZR_POOLD;
    const float* cnt   = g_zregion + ZR_CNT;
    int g = blockIdx.x, tid = threadIdx.x;
    float invc = 1.0f / fmaxf(cnt[g], 1.0f);
    for (int i = tid; i < LAT; i += blockDim.x) px[i] = poolX[g * LAT + i] * invc;
    if (tid == 0) spd = poolD[g] * invc;
    __syncthreads();
    if (tid < NCLASS) {
        float acc = g_c0[tid] + spd * g_v1[tid];
        for (int k = 0; k < LAT; k++) acc += px[k] * g_Wfin[k * NCLASS + tid];
        out[g * NCLASS + tid] = acc;
    }
}

// ---------------- launch ---------------------------------------------------
extern "C" void kernel_launch(void* const* d_in, const int* in_sizes, int n_in,
                              void* d_out, int out_size) {
    const float* fsnet = (const float*)d_in[0];
    const int*   src   = (const int*)d_in[1];
    const int*   dst   = (const int*)d_in[2];
    const int*   gid   = (const int*)d_in[3];
    const float* W_ext = (const float*)d_in[4];
    const float* b_ext = (const float*)d_in[5];
    const float* W1    = (const float*)d_in[6];
    const float* b1    = (const float*)d_in[7];
    const float* W2    = (const float*)d_in[8];
    const float* b2    = (const float*)d_in[9];
    const float* Wc    = (const float*)d_in[10];
    const float* bc    = (const float*)d_in[11];
    float* out = (float*)d_out;

    int n   = in_sizes[3];
    int E   = in_sizes[1];
    int RAW = in_sizes[4] / LAT;

    float *bufA, *bufB, *inv_out, *inv_in, *s1, *zreg;
    cudaGetSymbolAddress((void**)&bufA,    g_bufA);
    cudaGetSymbolAddress((void**)&bufB,    g_bufB);
    cudaGetSymbolAddress((void**)&inv_out, g_inv_out);
    cudaGetSymbolAddress((void**)&inv_in,  g_inv_in);
    cudaGetSymbolAddress((void**)&s1,      g_s1);
    cudaGetSymbolAddress((void**)&zreg,    g_zregion);

    int nb = (n + 1023) / 1024;

    // 0. zero packed scratch
    zero_kernel<<<148, 256>>>((float4*)zreg, ZR_TOTAL / 4);
    // 1. degree histograms
    degree_kernel<<<(E + 255) / 256, 256>>>(src, dst, E);
    // 2. per-chunk reduce + rsqrt factors + graph counts
    scanA_kernel<<<nb, 1024>>>(gid, n);
    // 3. GEMM0 (profiled slot): bufA = (fsnet @ W_ext + b_ext) * inv_out
    gemm0_kernel<<<(n + TM - 1) / TM, 256>>>(fsnet, W_ext, b_ext, inv_out, bufA, n, RAW);
    // 4/5. finish CSR offsets
    scanB_kernel<<<1, 128>>>(nb, n);
    scanC_kernel<<<nb, 1024>>>(n);
    // 6. CSR scatter (by dst)
    scatter_kernel<<<(E + 255) / 256, 256>>>(src, dst, E);
    // 7-9. fold weights
    wprec1_kernel<<<(LAT * H2 + 255) / 256, 256>>>(W1, W2);
    wprec2_kernel<<<(LAT * NCLASS + 255) / 256, 256>>>(Wc);
    wprec3_kernel<<<1, 256>>>(b1, W2, b2, Wc, bc);
    // 10. prop1: bufB = P(x0) * inv_in * inv_out
    int pblocks = (n * 32 + 255) / 256;
    prop_csr_kernel<false><<<pblocks, 256>>>((const float4*)bufA, (float4*)bufB, s1, nullptr, n);
    // 11. prop2 fused with graph pooling
    prop_csr_kernel<true><<<pblocks, 256>>>((const float4*)bufB, nullptr, inv_in, gid, n);
    // 12. d~ pooled by graph
    dtilde_kernel<<<pblocks, 256>>>(gid, n);
    // 13. out = (poolX/cnt) @ Wfin + (poolD/cnt) * v1 + c0
    final_kernel<<<NGRAPH, 128>>>(out);
}

// round 7
// speedup vs baseline: 1.8327x; 1.0792x over previous
#include <cuda_runtime.h>
#include <cstdint>

#define MAX_NODES 50000
#define LAT       100
#define NGRAPH    256
#define H2        200
#define NCLASS    55
#define MAX_EDGES 800000

typedef unsigned long long u64;

// ---------------- scratch (device globals) ---------------------------------
__device__ __align__(16) float g_bufA[MAX_NODES * LAT];   // x0 * inv_out
__device__ __align__(16) float g_bufB[MAX_NODES * LAT];   // P(x0) * inv_in * inv_out
__device__ __align__(16) float g_inv_out[MAX_NODES];
__device__ __align__(16) float g_inv_in[MAX_NODES];
__device__ __align__(16) float g_s1[MAX_NODES];           // inv_in * inv_out
__device__ __align__(16) int   g_off[MAX_NODES + 16];
__device__ __align__(16) int   g_cur[MAX_NODES];
__device__ __align__(16) int   g_csr[MAX_EDGES];
__device__ __align__(16) int   g_bsum[80];
__device__ __align__(16) int   g_bpre[80];
__device__ __align__(16) float g_W12[LAT * H2];           // W1 @ W2
__device__ __align__(16) float g_Wfin[LAT * NCLASS];      // W1 @ W2 @ Wc
__device__ __align__(16) float g_v1[64];                  // b1 @ W2 @ Wc
__device__ __align__(16) float g_c0[64];                  // b2 @ Wc + bc

// packed zero region: out_deg(f32) | deg_in(i32) | poolX | poolD | cnt
#define ZR_OUTDEG 0
#define ZR_DEGIN  50000
#define ZR_POOLX  100000
#define ZR_POOLD  125600
#define ZR_CNT    125856
#define ZR_TOTAL  126112
__device__ __align__(16) float g_zregion[ZR_TOTAL];

// ---------------- f32x2 packed math helpers --------------------------------
__device__ __forceinline__ void ffma2(u64& d, u64 a, u64 b) {
    asm("fma.rn.f32x2 %0, %1, %2, %0;" : "+l"(d) : "l"(a), "l"(b));
}
__device__ __forceinline__ float2 unpack2(u64 v) {
    float2 f; asm("mov.b64 {%0, %1}, %2;" : "=f"(f.x), "=f"(f.y) : "l"(v)); return f;
}
__device__ __forceinline__ u64 swap2(u64 v) {
    float2 f = unpack2(v);
    u64 r; asm("mov.b64 %0, {%1, %2};" : "=l"(r) : "f"(f.y), "f"(f.x));
    return r;
}

// ---------------- small kernels -------------------------------------------
__global__ void zero_kernel(float4* p, int n4) {
    int i = blockIdx.x * blockDim.x + threadIdx.x;
    float4 z = make_float4(0.f, 0.f, 0.f, 0.f);
    for (; i < n4; i += gridDim.x * blockDim.x) p[i] = z;
}

__global__ void degree_kernel(const int* __restrict__ src, const int* __restrict__ dst, int E) {
    float* out_deg = g_zregion + ZR_OUTDEG;
    int*   deg_in  = (int*)(g_zregion + ZR_DEGIN);
    int i = blockIdx.x * blockDim.x + threadIdx.x;
    if (i < E) {
        atomicAdd(&out_deg[src[i]], 1.0f);
        atomicAdd(&deg_in[dst[i]], 1);
    }
}

// scanA: per-chunk reduce of deg_in; also rsqrt factors + per-graph counts
__global__ void scanA_kernel(const int* __restrict__ gid, int n) {
    __shared__ int wsum[32];
    const float* out_deg = g_zregion + ZR_OUTDEG;
    const int*   deg_in  = (const int*)(g_zregion + ZR_DEGIN);
    float* cnt = g_zregion + ZR_CNT;
    int tid = threadIdx.x, lane = tid & 31, warp = tid >> 5;
    int i = blockIdx.x * 1024 + tid;
    int v = 0;
    if (i < n) {
        v = deg_in[i];
        float ii = rsqrtf(fmaxf((float)v, 1.0f));
        float io = rsqrtf(fmaxf(out_deg[i], 1.0f));
        g_inv_in[i]  = ii;
        g_inv_out[i] = io;
        g_s1[i]      = ii * io;
        atomicAdd(&cnt[gid[i]], 1.0f);
    }
    int s = v;
#pragma unroll
    for (int d = 16; d > 0; d >>= 1) s += __shfl_down_sync(0xffffffffu, s, d);
    if (lane == 0) wsum[warp] = s;
    __syncthreads();
    if (warp == 0) {
        int t = (lane < 32) ? wsum[lane] : 0;
#pragma unroll
        for (int d = 16; d > 0; d >>= 1) t += __shfl_down_sync(0xffffffffu, t, d);
        if (lane == 0) g_bsum[blockIdx.x] = t;
    }
}

// scanB: exclusive scan of block sums (tiny)
__global__ void scanB_kernel(int nb, int n) {
    __shared__ int s[80];
    int tid = threadIdx.x;
    if (tid < nb) s[tid] = g_bsum[tid];
    __syncthreads();
    if (tid == 0) {
        int run = 0;
        for (int b = 0; b < nb; b++) { int t = s[b]; s[b] = run; run += t; }
        g_off[n] = run;
    }
    __syncthreads();
    if (tid < nb) g_bpre[tid] = s[tid];
}

// scanC: local exclusive scan + block prefix -> off/cur
__global__ void scanC_kernel(int n) {
    __shared__ int wsum[32];
    const int* deg_in = (const int*)(g_zregion + ZR_DEGIN);
    int tid = threadIdx.x, lane = tid & 31, warp = tid >> 5;
    int i = blockIdx.x * 1024 + tid;
    int v = (i < n) ? deg_in[i] : 0;
    int s = v;
#pragma unroll
    for (int d = 1; d < 32; d <<= 1) {
        int t = __shfl_up_sync(0xffffffffu, s, d);
        if (lane >= d) s += t;
    }
    if (lane == 31) wsum[warp] = s;
    __syncthreads();
    if (warp == 0) {
        int ws = wsum[lane];
#pragma unroll
        for (int d = 1; d < 32; d <<= 1) {
            int t = __shfl_up_sync(0xffffffffu, ws, d);
            if (lane >= d) ws += t;
        }
        wsum[lane] = ws;
    }
    __syncthreads();
    int wpre = (warp > 0) ? wsum[warp - 1] : 0;
    int excl = s - v + wpre + g_bpre[blockIdx.x];
    if (i < n) { g_off[i] = excl; g_cur[i] = excl; }
}

__global__ void scatter_kernel(const int* __restrict__ src, const int* __restrict__ dst, int E) {
    int i = blockIdx.x * blockDim.x + threadIdx.x;
    if (i < E) {
        int p = atomicAdd(&g_cur[dst[i]], 1);
        g_csr[p] = src[i];
    }
}

// ---------------- CSR propagation -----------------------------------------
// POOL=false: agg row write; lane 25 also accumulates dtilde = sum(inv_out[src])
//             and pool-atomics it (fused former dtilde_kernel).
// POOL=true:  rows pooled by graph into poolX.
template <bool POOL>
__global__ void prop_csr_kernel(const float4* __restrict__ xs,
                                float4* __restrict__ agg,
                                const float* __restrict__ scale,
                                const int* __restrict__ gid, int n) {
    int node = (blockIdx.x * blockDim.x + threadIdx.x) >> 5;
    int lane = threadIdx.x & 31;
    if (node >= n) return;
    int b = g_off[node], e = g_off[node + 1];
    bool act = lane < 25;
    bool dt  = (!POOL) && (lane == 25);
    float4 a0 = make_float4(0.f, 0.f, 0.f, 0.f);
    float4 a1 = a0, a2 = a0, a3 = a0;
    float sd = 0.f;
    unsigned base = (unsigned)lane;
    int k = b;
    for (; k + 4 <= e; k += 4) {
        int s0 = g_csr[k], s1 = g_csr[k + 1], s2 = g_csr[k + 2], s3 = g_csr[k + 3];
        if (act) {
            float4 v0 = xs[(unsigned)s0 * 25u + base];
            float4 v1 = xs[(unsigned)s1 * 25u + base];
            float4 v2 = xs[(unsigned)s2 * 25u + base];
            float4 v3 = xs[(unsigned)s3 * 25u + base];
            a0.x += v0.x; a0.y += v0.y; a0.z += v0.z; a0.w += v0.w;
            a1.x += v1.x; a1.y += v1.y; a1.z += v1.z; a1.w += v1.w;
            a2.x += v2.x; a2.y += v2.y; a2.z += v2.z; a2.w += v2.w;
            a3.x += v3.x; a3.y += v3.y; a3.z += v3.z; a3.w += v3.w;
        } else if (dt) {
            sd += g_inv_out[s0] + g_inv_out[s1] + g_inv_out[s2] + g_inv_out[s3];
        }
    }
    for (; k < e; k++) {
        int s0 = g_csr[k];
        if (act) {
            float4 v0 = xs[(unsigned)s0 * 25u + base];
            a0.x += v0.x; a0.y += v0.y; a0.z += v0.z; a0.w += v0.w;
        } else if (dt) {
            sd += g_inv_out[s0];
        }
    }
    if (act) {
        float sc = scale[node];
        float x = (a0.x + a1.x + a2.x + a3.x) * sc;
        float y = (a0.y + a1.y + a2.y + a3.y) * sc;
        float z = (a0.z + a1.z + a2.z + a3.z) * sc;
        float w = (a0.w + a1.w + a2.w + a3.w) * sc;
        if (!POOL) {
            agg[(unsigned)node * 25u + base] = make_float4(x, y, z, w);
        } else {
            float* poolX = g_zregion + ZR_POOLX;
            float* p = poolX + (unsigned)gid[node] * 100u + base * 4u;
            asm volatile("red.global.add.v4.f32 [%0], {%1,%2,%3,%4};"
                         :: "l"(p), "f"(x), "f"(y), "f"(z), "f"(w)
                         : "memory");
        }
    } else if (dt) {
        float* poolD = g_zregion + ZR_POOLD;
        atomicAdd(&poolD[gid[node]], sd * g_inv_in[node]);
    }
}

// ---------------- GEMM0: C = (A @ W + b) .* sout ---------------------------
// 512 threads, block tile 160 x 100, K-chunk 32, DOUBLE-BUFFERED smem with
// register prefetch: chunk ch+1's global loads are issued before computing
// chunk ch, so L2 latency hides under ~1100 cyc of FFMA2s. 500 workers,
// each 8 rows x 4 cols. Per k: 3x LDS.128 + 2 swaps + 16 FFMA2 (32 FMAs).
#define TM 160
#define KC 32
#define SA 164
#define SW 104
#define ABUF (KC * SA)
#define WBUF (KC * SW)
#define GSMEM ((2 * ABUF + 2 * WBUF) * 4)
__global__ void __launch_bounds__(512, 1) gemm0_kernel(
        const float* __restrict__ A,
        const float* __restrict__ W,
        const float* __restrict__ bias,
        const float* __restrict__ sout,
        float* __restrict__ C, int M, int K) {
    extern __shared__ float sm[];
    float* AsB = sm;                 // [2][KC][SA]
    float* WsB = sm + 2 * ABUF;      // [2][KC][SW]

    int tid = threadIdx.x;
    int m0 = blockIdx.x * TM;
    bool worker = tid < 500;
    int ty = tid / 25;               // 0..19 for workers
    int tx = tid - ty * 25;          // 0..24
    int r0 = ty * 8;
    int c0 = tx * 4;

    u64 accd[4][2], accx[4][2];
#pragma unroll
    for (int p = 0; p < 4; p++) {
        accd[p][0] = accd[p][1] = 0ull;
        accx[p][0] = accx[p][1] = 0ull;
    }

    // staging register buffers
    float4 aQ[3], wQ[2];

    int nk = (K + KC - 1) / KC;

    // ---- prologue: load chunk 0 ----
#pragma unroll
    for (int s = 0; s < 3; s++) {
        int idx = tid + s * 512;
        if (idx < 1280) {
            int row = idx >> 3, q = idx & 7;
            int gr = m0 + row; if (gr >= M) gr = M - 1;
            int gk = q * 4;
            if (gk + 3 < K) {
                aQ[s] = *(const float4*)&A[(size_t)gr * K + gk];
            } else {
                aQ[s].x = (gk     < K) ? A[(size_t)gr * K + gk]     : 0.f;
                aQ[s].y = (gk + 1 < K) ? A[(size_t)gr * K + gk + 1] : 0.f;
                aQ[s].z = (gk + 2 < K) ? A[(size_t)gr * K + gk + 2] : 0.f;
                aQ[s].w = (gk + 3 < K) ? A[(size_t)gr * K + gk + 3] : 0.f;
            }
        }
    }
#pragma unroll
    for (int s = 0; s < 2; s++) {
        int idx = tid + s * 512;
        if (idx < 800) {
            int kk = idx / 25, c4 = idx - kk * 25;
            wQ[s] = (kk < K) ? *(const float4*)&W[(size_t)kk * LAT + c4 * 4]
                             : make_float4(0.f, 0.f, 0.f, 0.f);
        }
    }
    // store chunk 0 -> buf 0
#pragma unroll
    for (int s = 0; s < 3; s++) {
        int idx = tid + s * 512;
        if (idx < 1280) {
            int row = idx >> 3, q = idx & 7;
            float* dst = AsB + (q * 4) * SA + row;
            dst[0] = aQ[s].x; dst[SA] = aQ[s].y; dst[2 * SA] = aQ[s].z; dst[3 * SA] = aQ[s].w;
        }
    }
#pragma unroll
    for (int s = 0; s < 2; s++) {
        int idx = tid + s * 512;
        if (idx < 800) {
            int kk = idx / 25, c4 = idx - kk * 25;
            *(float4*)&WsB[kk * SW + c4 * 4] = wQ[s];
        }
    }
    __syncthreads();

    for (int ch = 0; ch < nk; ch++) {
        int buf = ch & 1;
        // prefetch chunk ch+1 into registers (latency hides under compute)
        if (ch + 1 < nk) {
            int k0 = (ch + 1) * KC;
#pragma unroll
            for (int s = 0; s < 3; s++) {
                int idx = tid + s * 512;
                if (idx < 1280) {
                    int row = idx >> 3, q = idx & 7;
                    int gr = m0 + row; if (gr >= M) gr = M - 1;
                    int gk = k0 + q * 4;
                    if (gk + 3 < K) {
                        aQ[s] = *(const float4*)&A[(size_t)gr * K + gk];
                    } else {
                        aQ[s].x = (gk     < K) ? A[(size_t)gr * K + gk]     : 0.f;
                        aQ[s].y = (gk + 1 < K) ? A[(size_t)gr * K + gk + 1] : 0.f;
                        aQ[s].z = (gk + 2 < K) ? A[(size_t)gr * K + gk + 2] : 0.f;
                        aQ[s].w = (gk + 3 < K) ? A[(size_t)gr * K + gk + 3] : 0.f;
                    }
                }
            }
#pragma unroll
            for (int s = 0; s < 2; s++) {
                int idx = tid + s * 512;
                if (idx < 800) {
                    int kk = idx / 25, c4 = idx - kk * 25;
                    int gk = k0 + kk;
                    wQ[s] = (gk < K) ? *(const float4*)&W[(size_t)gk * LAT + c4 * 4]
                                     : make_float4(0.f, 0.f, 0.f, 0.f);
                }
            }
        }
        // compute from smem[buf]
        if (worker) {
            const float* Ab = AsB + buf * ABUF;
            const float* Wb = WsB + buf * WBUF;
#pragma unroll 4
            for (int k = 0; k < KC; k++) {
                ulonglong2 a01 = *(const ulonglong2*)(Ab + k * SA + r0);
                ulonglong2 a23 = *(const ulonglong2*)(Ab + k * SA + r0 + 4);
                ulonglong2 w   = *(const ulonglong2*)(Wb + k * SW + c0);
                u64 wxs = swap2(w.x);
                u64 wys = swap2(w.y);
                ffma2(accd[0][0], a01.x, w.x);  ffma2(accx[0][0], a01.x, wxs);
                ffma2(accd[0][1], a01.x, w.y);  ffma2(accx[0][1], a01.x, wys);
                ffma2(accd[1][0], a01.y, w.x);  ffma2(accx[1][0], a01.y, wxs);
                ffma2(accd[1][1], a01.y, w.y);  ffma2(accx[1][1], a01.y, wys);
                ffma2(accd[2][0], a23.x, w.x);  ffma2(accx[2][0], a23.x, wxs);
                ffma2(accd[2][1], a23.x, w.y);  ffma2(accx[2][1], a23.x, wys);
                ffma2(accd[3][0], a23.y, w.x);  ffma2(accx[3][0], a23.y, wxs);
                ffma2(accd[3][1], a23.y, w.y);  ffma2(accx[3][1], a23.y, wys);
            }
        }
        // store prefetched chunk to the other buffer
        if (ch + 1 < nk) {
            float* An = AsB + (buf ^ 1) * ABUF;
            float* Wn = WsB + (buf ^ 1) * WBUF;
#pragma unroll
            for (int s = 0; s < 3; s++) {
                int idx = tid + s * 512;
                if (idx < 1280) {
                    int row = idx >> 3, q = idx & 7;
                    float* dst = An + (q * 4) * SA + row;
                    dst[0] = aQ[s].x; dst[SA] = aQ[s].y; dst[2 * SA] = aQ[s].z; dst[3 * SA] = aQ[s].w;
                }
            }
#pragma unroll
            for (int s = 0; s < 2; s++) {
                int idx = tid + s * 512;
                if (idx < 800) {
                    int kk = idx / 25, c4 = idx - kk * 25;
                    *(float4*)&Wn[kk * SW + c4 * 4] = wQ[s];
                }
            }
            __syncthreads();
        }
    }

    if (worker) {
        float4 bv = *(const float4*)&bias[c0];
#pragma unroll
        for (int p = 0; p < 4; p++) {
            float2 d0 = unpack2(accd[p][0]);
            float2 x0 = unpack2(accx[p][0]);
            float2 d1 = unpack2(accd[p][1]);
            float2 x1 = unpack2(accx[p][1]);
            int row = m0 + r0 + 2 * p;
            if (row < M) {
                float so = sout[row];
                float4 v = make_float4((d0.x + bv.x) * so, (x0.x + bv.y) * so,
                                       (d1.x + bv.z) * so, (x1.x + bv.w) * so);
                *(float4*)&C[(size_t)row * LAT + c0] = v;
            }
            if (row + 1 < M) {
                float so = sout[row + 1];
                float4 v = make_float4((x0.y + bv.x) * so, (d0.y + bv.y) * so,
                                       (x1.y + bv.z) * so, (d1.y + bv.w) * so);
                *(float4*)&C[(size_t)(row + 1) * LAT + c0] = v;
            }
        }
    }
}

// ---------------- weight folding (all tiny) --------------------------------
__global__ void wprec1_kernel(const float* __restrict__ W1, const float* __restrict__ W2) {
    int idx = blockIdx.x * blockDim.x + threadIdx.x;
    if (idx >= LAT * H2) return;
    int i = idx / H2, j = idx % H2;
    float acc = 0.f;
    for (int k = 0; k < LAT; k++) acc += W1[i * LAT + k] * W2[k * H2 + j];
    g_W12[idx] = acc;
}
__global__ void wprec2_kernel(const float* __restrict__ Wc) {
    int idx = blockIdx.x * blockDim.x + threadIdx.x;
    if (idx >= LAT * NCLASS) return;
    int i = idx / NCLASS, j = idx % NCLASS;
    float acc = 0.f;
    for (int k = 0; k < H2; k++) acc += g_W12[i * H2 + k] * Wc[k * NCLASS + j];
    g_Wfin[idx] = acc;
}
__global__ void wprec3_kernel(const float* __restrict__ b1, const float* __restrict__ W2,
                              const float* __restrict__ b2, const float* __restrict__ Wc,
                              const float* __restrict__ bc) {
    __shared__ float bw2[H2];
    int tid = threadIdx.x;
    for (int k = tid; k < H2; k += blockDim.x) {
        float acc = 0.f;
        for (int j = 0; j < LAT; j++) acc += b1[j] * W2[j * H2 + k];
        bw2[k] = acc;
    }
    __syncthreads();
    if (tid < NCLASS) {
        float v = 0.f, c = 0.f;
        for (int k = 0; k < H2; k++) {
            v += bw2[k] * Wc[k * NCLASS + tid];
            c += b2[k] * Wc[k * NCLASS + tid];
        }
        g_v1[tid] = v;
        g_c0[tid] = c + bc[tid];
    }
}

// ---------------- final: out[g,c] ------------------------------------------
__global__ void final_kernel(float* __restrict__ out) {
    __shared__ float px[LAT];
    __shared__ float spd;
    const float* poolX = g_zregion + ZR_POOLX;
    const float* poolD = g_zregion + ZR_POOLD;
    const float* cnt   = g_zregion + ZR_CNT;
    int g = blockIdx.x, tid = threadIdx.x;
    float invc = 1.0f / fmaxf(cnt[g], 1.0f);
    for (int i = tid; i < LAT; i += blockDim.x) px[i] = poolX[g * LAT + i] * invc;
    if (tid == 0) spd = poolD[g] * invc;
    __syncthreads();
    if (tid < NCLASS) {
        float acc = g_c0[tid] + spd * g_v1[tid];
        for (int k = 0; k < LAT; k++) acc += px[k] * g_Wfin[k * NCLASS + tid];
        out[g * NCLASS + tid] = acc;
    }
}

// ---------------- launch ---------------------------------------------------
extern "C" void kernel_launch(void* const* d_in, const int* in_sizes, int n_in,
                              void* d_out, int out_size) {
    const float* fsnet = (const float*)d_in[0];
    const int*   src   = (const int*)d_in[1];
    const int*   dst   = (const int*)d_in[2];
    const int*   gid   = (const int*)d_in[3];
    const float* W_ext = (const float*)d_in[4];
    const float* b_ext = (const float*)d_in[5];
    const float* W1    = (const float*)d_in[6];
    const float* b1    = (const float*)d_in[7];
    const float* W2    = (const float*)d_in[8];
    const float* b2    = (const float*)d_in[9];
    const float* Wc    = (const float*)d_in[10];
    const float* bc    = (const float*)d_in[11];
    float* out = (float*)d_out;

    int n   = in_sizes[3];
    int E   = in_sizes[1];
    int RAW = in_sizes[4] / LAT;

    float *bufA, *bufB, *inv_out, *inv_in, *s1, *zreg;
    cudaGetSymbolAddress((void**)&bufA,    g_bufA);
    cudaGetSymbolAddress((void**)&bufB,    g_bufB);
    cudaGetSymbolAddress((void**)&inv_out, g_inv_out);
    cudaGetSymbolAddress((void**)&inv_in,  g_inv_in);
    cudaGetSymbolAddress((void**)&s1,      g_s1);
    cudaGetSymbolAddress((void**)&zreg,    g_zregion);

    cudaFuncSetAttribute(gemm0_kernel,
                         cudaFuncAttributeMaxDynamicSharedMemorySize, GSMEM);

    int nb = (n + 1023) / 1024;

    // 0. zero packed scratch
    zero_kernel<<<148, 256>>>((float4*)zreg, ZR_TOTAL / 4);
    // 1. degree histograms
    degree_kernel<<<(E + 255) / 256, 256>>>(src, dst, E);
    // 2. per-chunk reduce + rsqrt factors + graph counts
    scanA_kernel<<<nb, 1024>>>(gid, n);
    // 3. GEMM0 (profiled slot): bufA = (fsnet @ W_ext + b_ext) * inv_out
    gemm0_kernel<<<(n + TM - 1) / TM, 512, GSMEM>>>(fsnet, W_ext, b_ext, inv_out, bufA, n, RAW);
    // 4/5. finish CSR offsets
    scanB_kernel<<<1, 128>>>(nb, n);
    scanC_kernel<<<nb, 1024>>>(n);
    // 6. CSR scatter (by dst)
    scatter_kernel<<<(E + 255) / 256, 256>>>(src, dst, E);
    // 7-9. fold weights
    wprec1_kernel<<<(LAT * H2 + 255) / 256, 256>>>(W1, W2);
    wprec2_kernel<<<(LAT * NCLASS + 255) / 256, 256>>>(Wc);
    wprec3_kernel<<<1, 256>>>(b1, W2, b2, Wc, bc);
    // 10. prop1 (+ fused dtilde on lane 25): bufB = P(x0) * s1
    int pblocks = (n * 32 + 255) / 256;
    prop_csr_kernel<false><<<pblocks, 256>>>((const float4*)bufA, (float4*)bufB, s1, gid, n);
    // 11. prop2 fused with graph pooling
    prop_csr_kernel<true><<<pblocks, 256>>>((const float4*)bufB, nullptr, inv_in, gid, n);
    // 12. out = (poolX/cnt) @ Wfin + (poolD/cnt) * v1 + c0
    final_kernel<<<NGRAPH, 128>>>(out);
}

// round 8
// speedup vs baseline: 1.9274x; 1.0517x over previous
#include <cuda_runtime.h>
#include <cstdint>

#define MAX_NODES 50000
#define LAT       100
#define NGRAPH    256
#define H2        200
#define NCLASS    55
#define MAX_EDGES 800000

typedef unsigned long long u64;

// ---------------- scratch (device globals) ---------------------------------
__device__ __align__(16) float g_bufA[MAX_NODES * LAT];   // x0 * inv_out
__device__ __align__(16) float g_bufB[MAX_NODES * LAT];   // P(x0) * inv_in * inv_out
__device__ __align__(16) float g_inv_out[MAX_NODES];
__device__ __align__(16) float g_inv_in[MAX_NODES];
__device__ __align__(16) float g_s1[MAX_NODES];           // inv_in * inv_out
__device__ __align__(16) int   g_off[MAX_NODES + 16];
__device__ __align__(16) int   g_cur[MAX_NODES];
__device__ __align__(16) int   g_csr[MAX_EDGES];
__device__ __align__(16) int   g_bsum[80];
__device__ __align__(16) int   g_bpre[80];
__device__ __align__(16) float g_W12[LAT * H2];           // W1 @ W2
__device__ __align__(16) float g_Wfin[LAT * NCLASS];      // W1 @ W2 @ Wc
__device__ __align__(16) float g_v1[64];                  // b1 @ W2 @ Wc
__device__ __align__(16) float g_c0[64];                  // b2 @ Wc + bc

// packed zero region: out_deg(f32) | deg_in(i32) | poolX | poolD | cnt
#define ZR_OUTDEG 0
#define ZR_DEGIN  50000
#define ZR_POOLX  100000
#define ZR_POOLD  125600
#define ZR_CNT    125856
#define ZR_TOTAL  126112
__device__ __align__(16) float g_zregion[ZR_TOTAL];

// ---------------- f32x2 packed math helpers --------------------------------
__device__ __forceinline__ void ffma2(u64& d, u64 a, u64 b) {
    asm("fma.rn.f32x2 %0, %1, %2, %0;" : "+l"(d) : "l"(a), "l"(b));
}
__device__ __forceinline__ float2 unpack2(u64 v) {
    float2 f; asm("mov.b64 {%0, %1}, %2;" : "=f"(f.x), "=f"(f.y) : "l"(v)); return f;
}
__device__ __forceinline__ u64 swap2(u64 v) {
    float2 f = unpack2(v);
    u64 r; asm("mov.b64 %0, {%1, %2};" : "=l"(r) : "f"(f.y), "f"(f.x));
    return r;
}

// ---------------- cp.async helpers -----------------------------------------
__device__ __forceinline__ void cp_async16(uint32_t saddr, const void* gptr) {
    asm volatile("cp.async.ca.shared.global [%0], [%1], 16;"
                 :: "r"(saddr), "l"(gptr));
}
__device__ __forceinline__ void cp_commit() {
    asm volatile("cp.async.commit_group;");
}
__device__ __forceinline__ void cp_wait_all() {
    asm volatile("cp.async.wait_group 0;");
}

// ---------------- small kernels -------------------------------------------
__global__ void zero_kernel(float4* p, int n4) {
    int i = blockIdx.x * blockDim.x + threadIdx.x;
    float4 z = make_float4(0.f, 0.f, 0.f, 0.f);
    for (; i < n4; i += gridDim.x * blockDim.x) p[i] = z;
}

__global__ void degree_kernel(const int* __restrict__ src, const int* __restrict__ dst, int E) {
    float* out_deg = g_zregion + ZR_OUTDEG;
    int*   deg_in  = (int*)(g_zregion + ZR_DEGIN);
    int i = blockIdx.x * blockDim.x + threadIdx.x;
    if (i < E) {
        atomicAdd(&out_deg[src[i]], 1.0f);
        atomicAdd(&deg_in[dst[i]], 1);
    }
}

// scanA: per-chunk reduce of deg_in; also rsqrt factors + per-graph counts
__global__ void scanA_kernel(const int* __restrict__ gid, int n) {
    __shared__ int wsum[32];
    const float* out_deg = g_zregion + ZR_OUTDEG;
    const int*   deg_in  = (const int*)(g_zregion + ZR_DEGIN);
    float* cnt = g_zregion + ZR_CNT;
    int tid = threadIdx.x, lane = tid & 31, warp = tid >> 5;
    int i = blockIdx.x * 1024 + tid;
    int v = 0;
    if (i < n) {
        v = deg_in[i];
        float ii = rsqrtf(fmaxf((float)v, 1.0f));
        float io = rsqrtf(fmaxf(out_deg[i], 1.0f));
        g_inv_in[i]  = ii;
        g_inv_out[i] = io;
        g_s1[i]      = ii * io;
        atomicAdd(&cnt[gid[i]], 1.0f);
    }
    int s = v;
#pragma unroll
    for (int d = 16; d > 0; d >>= 1) s += __shfl_down_sync(0xffffffffu, s, d);
    if (lane == 0) wsum[warp] = s;
    __syncthreads();
    if (warp == 0) {
        int t = (lane < 32) ? wsum[lane] : 0;
#pragma unroll
        for (int d = 16; d > 0; d >>= 1) t += __shfl_down_sync(0xffffffffu, t, d);
        if (lane == 0) g_bsum[blockIdx.x] = t;
    }
}

// scanB: exclusive scan of block sums (tiny)
__global__ void scanB_kernel(int nb, int n) {
    __shared__ int s[80];
    int tid = threadIdx.x;
    if (tid < nb) s[tid] = g_bsum[tid];
    __syncthreads();
    if (tid == 0) {
        int run = 0;
        for (int b = 0; b < nb; b++) { int t = s[b]; s[b] = run; run += t; }
        g_off[n] = run;
    }
    __syncthreads();
    if (tid < nb) g_bpre[tid] = s[tid];
}

// scanC: local exclusive scan + block prefix -> off/cur
__global__ void scanC_kernel(int n) {
    __shared__ int wsum[32];
    const int* deg_in = (const int*)(g_zregion + ZR_DEGIN);
    int tid = threadIdx.x, lane = tid & 31, warp = tid >> 5;
    int i = blockIdx.x * 1024 + tid;
    int v = (i < n) ? deg_in[i] : 0;
    int s = v;
#pragma unroll
    for (int d = 1; d < 32; d <<= 1) {
        int t = __shfl_up_sync(0xffffffffu, s, d);
        if (lane >= d) s += t;
    }
    if (lane == 31) wsum[warp] = s;
    __syncthreads();
    if (warp == 0) {
        int ws = wsum[lane];
#pragma unroll
        for (int d = 1; d < 32; d <<= 1) {
            int t = __shfl_up_sync(0xffffffffu, ws, d);
            if (lane >= d) ws += t;
        }
        wsum[lane] = ws;
    }
    __syncthreads();
    int wpre = (warp > 0) ? wsum[warp - 1] : 0;
    int excl = s - v + wpre + g_bpre[blockIdx.x];
    if (i < n) { g_off[i] = excl; g_cur[i] = excl; }
}

__global__ void scatter_kernel(const int* __restrict__ src, const int* __restrict__ dst, int E) {
    int i = blockIdx.x * blockDim.x + threadIdx.x;
    if (i < E) {
        int p = atomicAdd(&g_cur[dst[i]], 1);
        g_csr[p] = src[i];
    }
}

// ---------------- CSR propagation -----------------------------------------
// POOL=false: agg row write; lane 25 also accumulates dtilde = sum(inv_out[src])
// POOL=true:  rows pooled by graph into poolX.
template <bool POOL>
__global__ void prop_csr_kernel(const float4* __restrict__ xs,
                                float4* __restrict__ agg,
                                const float* __restrict__ scale,
                                const int* __restrict__ gid, int n) {
    int node = (blockIdx.x * blockDim.x + threadIdx.x) >> 5;
    int lane = threadIdx.x & 31;
    if (node >= n) return;
    int b = g_off[node], e = g_off[node + 1];
    bool act = lane < 25;
    bool dt  = (!POOL) && (lane == 25);
    float4 a0 = make_float4(0.f, 0.f, 0.f, 0.f);
    float4 a1 = a0, a2 = a0, a3 = a0;
    float sd = 0.f;
    unsigned base = (unsigned)lane;
    int k = b;
    for (; k + 4 <= e; k += 4) {
        int s0 = g_csr[k], s1 = g_csr[k + 1], s2 = g_csr[k + 2], s3 = g_csr[k + 3];
        if (act) {
            float4 v0 = xs[(unsigned)s0 * 25u + base];
            float4 v1 = xs[(unsigned)s1 * 25u + base];
            float4 v2 = xs[(unsigned)s2 * 25u + base];
            float4 v3 = xs[(unsigned)s3 * 25u + base];
            a0.x += v0.x; a0.y += v0.y; a0.z += v0.z; a0.w += v0.w;
            a1.x += v1.x; a1.y += v1.y; a1.z += v1.z; a1.w += v1.w;
            a2.x += v2.x; a2.y += v2.y; a2.z += v2.z; a2.w += v2.w;
            a3.x += v3.x; a3.y += v3.y; a3.z += v3.z; a3.w += v3.w;
        } else if (dt) {
            sd += g_inv_out[s0] + g_inv_out[s1] + g_inv_out[s2] + g_inv_out[s3];
        }
    }
    for (; k < e; k++) {
        int s0 = g_csr[k];
        if (act) {
            float4 v0 = xs[(unsigned)s0 * 25u + base];
            a0.x += v0.x; a0.y += v0.y; a0.z += v0.z; a0.w += v0.w;
        } else if (dt) {
            sd += g_inv_out[s0];
        }
    }
    if (act) {
        float sc = scale[node];
        float x = (a0.x + a1.x + a2.x + a3.x) * sc;
        float y = (a0.y + a1.y + a2.y + a3.y) * sc;
        float z = (a0.z + a1.z + a2.z + a3.z) * sc;
        float w = (a0.w + a1.w + a2.w + a3.w) * sc;
        if (!POOL) {
            agg[(unsigned)node * 25u + base] = make_float4(x, y, z, w);
        } else {
            float* poolX = g_zregion + ZR_POOLX;
            float* p = poolX + (unsigned)gid[node] * 100u + base * 4u;
            asm volatile("red.global.add.v4.f32 [%0], {%1,%2,%3,%4};"
                         :: "l"(p), "f"(x), "f"(y), "f"(z), "f"(w)
                         : "memory");
        }
    } else if (dt) {
        float* poolD = g_zregion + ZR_POOLD;
        atomicAdd(&poolD[gid[node]], sd * g_inv_in[node]);
    }
}

// ---------------- GEMM0: C = (A @ W + b) .* sout ---------------------------
// v3: 256 threads, TM=80, 3 blocks/SM (24 warps) for latency hiding.
// Double-buffered; W staged via cp.async (natural layout), A via
// LDG->reg->transposed STS. 250 workers, 8 rows x 4 cols each.
#define TM 80
#define KC 32
#define SA 84
#define SW 104
#define ABUF (KC * SA)
#define WBUF (KC * SW)
#define GSMEM ((2 * ABUF + 2 * WBUF) * 4)
__global__ void __launch_bounds__(256, 3) gemm0_kernel(
        const float* __restrict__ A,
        const float* __restrict__ W,
        const float* __restrict__ bias,
        const float* __restrict__ sout,
        float* __restrict__ C, int M, int K) {
    extern __shared__ float sm[];
    float* AsB = sm;                 // [2][KC][SA]
    float* WsB = sm + 2 * ABUF;      // [2][KC][SW]
    uint32_t wsmem = (uint32_t)__cvta_generic_to_shared(WsB);

    int tid = threadIdx.x;
    int m0 = blockIdx.x * TM;
    bool worker = tid < 250;
    int ty = tid / 25;               // 0..9 for workers
    int tx = tid - ty * 25;          // 0..24
    int r0 = ty * 8;
    int c0 = tx * 4;

    u64 accd[4][2], accx[4][2];
#pragma unroll
    for (int p = 0; p < 4; p++) {
        accd[p][0] = accd[p][1] = 0ull;
        accx[p][0] = accx[p][1] = 0ull;
    }

    float4 aQ[3];
    int nk = (K + KC - 1) / KC;

    // W chunk loader: cp.async natural layout (global row == smem row)
    auto loadW = [&](int k0, int buf) {
#pragma unroll
        for (int s = 0; s < 4; s++) {
            int idx = tid + s * 256;
            if (idx < 800) {
                int kk = idx / 25, c4 = idx - kk * 25;
                int gk = k0 + kk;
                uint32_t dst = wsmem + (buf * WBUF + kk * SW + c4 * 4) * 4;
                if (gk < K) {
                    cp_async16(dst, &W[(size_t)gk * LAT + c4 * 4]);
                } else {
                    float* d = WsB + buf * WBUF + kk * SW + c4 * 4;
                    d[0] = d[1] = d[2] = d[3] = 0.f;
                }
            }
        }
    };
    // A chunk loader: global -> regs
    auto loadA = [&](int k0) {
#pragma unroll
        for (int s = 0; s < 3; s++) {
            int idx = tid + s * 256;
            if (idx < 640) {
                int row = idx >> 3, q = idx & 7;
                int gr = m0 + row; if (gr >= M) gr = M - 1;
                int gk = k0 + q * 4;
                if (gk + 3 < K) {
                    aQ[s] = *(const float4*)&A[(size_t)gr * K + gk];
                } else {
                    aQ[s].x = (gk     < K) ? A[(size_t)gr * K + gk]     : 0.f;
                    aQ[s].y = (gk + 1 < K) ? A[(size_t)gr * K + gk + 1] : 0.f;
                    aQ[s].z = (gk + 2 < K) ? A[(size_t)gr * K + gk + 2] : 0.f;
                    aQ[s].w = (gk + 3 < K) ? A[(size_t)gr * K + gk + 3] : 0.f;
                }
            }
        }
    };
    // A store: regs -> transposed smem
    auto storeA = [&](int buf) {
        float* Ab = AsB + buf * ABUF;
#pragma unroll
        for (int s = 0; s < 3; s++) {
            int idx = tid + s * 256;
            if (idx < 640) {
                int row = idx >> 3, q = idx & 7;
                float* dst = Ab + (q * 4) * SA + row;
                dst[0] = aQ[s].x; dst[SA] = aQ[s].y; dst[2 * SA] = aQ[s].z; dst[3 * SA] = aQ[s].w;
            }
        }
    };

    // ---- prologue: chunk 0 ----
    loadW(0, 0);
    cp_commit();
    loadA(0);
    storeA(0);
    cp_wait_all();
    __syncthreads();

    for (int ch = 0; ch < nk; ch++) {
        int buf = ch & 1;
        if (ch + 1 < nk) {
            loadA((ch + 1) * KC);
            loadW((ch + 1) * KC, buf ^ 1);
            cp_commit();
        }
        // compute from smem[buf]
        if (worker) {
            const float* Ab = AsB + buf * ABUF;
            const float* Wb = WsB + buf * WBUF;
#pragma unroll 4
            for (int k = 0; k < KC; k++) {
                ulonglong2 a01 = *(const ulonglong2*)(Ab + k * SA + r0);
                ulonglong2 a23 = *(const ulonglong2*)(Ab + k * SA + r0 + 4);
                ulonglong2 w   = *(const ulonglong2*)(Wb + k * SW + c0);
                u64 wxs = swap2(w.x);
                u64 wys = swap2(w.y);
                ffma2(accd[0][0], a01.x, w.x);  ffma2(accx[0][0], a01.x, wxs);
                ffma2(accd[0][1], a01.x, w.y);  ffma2(accx[0][1], a01.x, wys);
                ffma2(accd[1][0], a01.y, w.x);  ffma2(accx[1][0], a01.y, wxs);
                ffma2(accd[1][1], a01.y, w.y);  ffma2(accx[1][1], a01.y, wys);
                ffma2(accd[2][0], a23.x, w.x);  ffma2(accx[2][0], a23.x, wxs);
                ffma2(accd[2][1], a23.x, w.y);  ffma2(accx[2][1], a23.x, wys);
                ffma2(accd[3][0], a23.y, w.x);  ffma2(accx[3][0], a23.y, wxs);
                ffma2(accd[3][1], a23.y, w.y);  ffma2(accx[3][1], a23.y, wys);
            }
        }
        if (ch + 1 < nk) {
            storeA(buf ^ 1);
            cp_wait_all();
            __syncthreads();
        }
    }

    if (worker) {
        float4 bv = *(const float4*)&bias[c0];
#pragma unroll
        for (int p = 0; p < 4; p++) {
            float2 d0 = unpack2(accd[p][0]);
            float2 x0 = unpack2(accx[p][0]);
            float2 d1 = unpack2(accd[p][1]);
            float2 x1 = unpack2(accx[p][1]);
            int row = m0 + r0 + 2 * p;
            if (row < M) {
                float so = sout[row];
                float4 v = make_float4((d0.x + bv.x) * so, (x0.x + bv.y) * so,
                                       (d1.x + bv.z) * so, (x1.x + bv.w) * so);
                *(float4*)&C[(size_t)row * LAT + c0] = v;
            }
            if (row + 1 < M) {
                float so = sout[row + 1];
                float4 v = make_float4((x0.y + bv.x) * so, (d0.y + bv.y) * so,
                                       (x1.y + bv.z) * so, (d1.y + bv.w) * so);
                *(float4*)&C[(size_t)(row + 1) * LAT + c0] = v;
            }
        }
    }
}

// ---------------- weight folding (all tiny) --------------------------------
__global__ void wprec1_kernel(const float* __restrict__ W1, const float* __restrict__ W2) {
    int idx = blockIdx.x * blockDim.x + threadIdx.x;
    if (idx >= LAT * H2) return;
    int i = idx / H2, j = idx % H2;
    float acc = 0.f;
    for (int k = 0; k < LAT; k++) acc += W1[i * LAT + k] * W2[k * H2 + j];
    g_W12[idx] = acc;
}
__global__ void wprec2_kernel(const float* __restrict__ Wc) {
    int idx = blockIdx.x * blockDim.x + threadIdx.x;
    if (idx >= LAT * NCLASS) return;
    int i = idx / NCLASS, j = idx % NCLASS;
    float acc = 0.f;
    for (int k = 0; k < H2; k++) acc += g_W12[i * H2 + k] * Wc[k * NCLASS + j];
    g_Wfin[idx] = acc;
}
__global__ void wprec3_kernel(const float* __restrict__ b1, const float* __restrict__ W2,
                              const float* __restrict__ b2, const float* __restrict__ Wc,
                              const float* __restrict__ bc) {
    __shared__ float bw2[H2];
    int tid = threadIdx.x;
    for (int k = tid; k < H2; k += blockDim.x) {
        float acc = 0.f;
        for (int j = 0; j < LAT; j++) acc += b1[j] * W2[j * H2 + k];
        bw2[k] = acc;
    }
    __syncthreads();
    if (tid < NCLASS) {
        float v = 0.f, c = 0.f;
        for (int k = 0; k < H2; k++) {
            v += bw2[k] * Wc[k * NCLASS + tid];
            c += b2[k] * Wc[k * NCLASS + tid];
        }
        g_v1[tid] = v;
        g_c0[tid] = c + bc[tid];
    }
}

// ---------------- final: out[g,c] ------------------------------------------
__global__ void final_kernel(float* __restrict__ out) {
    __shared__ float px[LAT];
    __shared__ float spd;
    const float* poolX = g_zregion + ZR_POOLX;
    const float* poolD = g_zregion + ZR_POOLD;
    const float* cnt   = g_zregion + ZR_CNT;
    int g = blockIdx.x, tid = threadIdx.x;
    float invc = 1.0f / fmaxf(cnt[g], 1.0f);
    for (int i = tid; i < LAT; i += blockDim.x) px[i] = poolX[g * LAT + i] * invc;
    if (tid == 0) spd = poolD[g] * invc;
    __syncthreads();
    if (tid < NCLASS) {
        float acc = g_c0[tid] + spd * g_v1[tid];
        for (int k = 0; k < LAT; k++) acc += px[k] * g_Wfin[k * NCLASS + tid];
        out[g * NCLASS + tid] = acc;
    }
}

// ---------------- launch ---------------------------------------------------
extern "C" void kernel_launch(void* const* d_in, const int* in_sizes, int n_in,
                              void* d_out, int out_size) {
    const float* fsnet = (const float*)d_in[0];
    const int*   src   = (const int*)d_in[1];
    const int*   dst   = (const int*)d_in[2];
    const int*   gid   = (const int*)d_in[3];
    const float* W_ext = (const float*)d_in[4];
    const float* b_ext = (const float*)d_in[5];
    const float* W1    = (const float*)d_in[6];
    const float* b1    = (const float*)d_in[7];
    const float* W2    = (const float*)d_in[8];
    const float* b2    = (const float*)d_in[9];
    const float* Wc    = (const float*)d_in[10];
    const float* bc    = (const float*)d_in[11];
    float* out = (float*)d_out;

    int n   = in_sizes[3];
    int E   = in_sizes[1];
    int RAW = in_sizes[4] / LAT;

    float *bufA, *bufB, *inv_out, *inv_in, *s1, *zreg;
    cudaGetSymbolAddress((void**)&bufA,    g_bufA);
    cudaGetSymbolAddress((void**)&bufB,    g_bufB);
    cudaGetSymbolAddress((void**)&inv_out, g_inv_out);
    cudaGetSymbolAddress((void**)&inv_in,  g_inv_in);
    cudaGetSymbolAddress((void**)&s1,      g_s1);
    cudaGetSymbolAddress((void**)&zreg,    g_zregion);

    cudaFuncSetAttribute(gemm0_kernel,
                         cudaFuncAttributeMaxDynamicSharedMemorySize, GSMEM);

    int nb = (n + 1023) / 1024;

    // 0. zero packed scratch
    zero_kernel<<<148, 256>>>((float4*)zreg, ZR_TOTAL / 4);
    // 1. degree histograms
    degree_kernel<<<(E + 255) / 256, 256>>>(src, dst, E);
    // 2. per-chunk reduce + rsqrt factors + graph counts
    scanA_kernel<<<nb, 1024>>>(gid, n);
    // 3. GEMM0 (profiled slot): bufA = (fsnet @ W_ext + b_ext) * inv_out
    gemm0_kernel<<<(n + TM - 1) / TM, 256, GSMEM>>>(fsnet, W_ext, b_ext, inv_out, bufA, n, RAW);
    // 4/5. finish CSR offsets
    scanB_kernel<<<1, 128>>>(nb, n);
    scanC_kernel<<<nb, 1024>>>(n);
    // 6. CSR scatter (by dst)
    scatter_kernel<<<(E + 255) / 256, 256>>>(src, dst, E);
    // 7-9. fold weights
    wprec1_kernel<<<(LAT * H2 + 255) / 256, 256>>>(W1, W2);
    wprec2_kernel<<<(LAT * NCLASS + 255) / 256, 256>>>(Wc);
    wprec3_kernel<<<1, 256>>>(b1, W2, b2, Wc, bc);
    // 10. prop1 (+ fused dtilde on lane 25): bufB = P(x0) * s1
    int pblocks = (n * 32 + 255) / 256;
    prop_csr_kernel<false><<<pblocks, 256>>>((const float4*)bufA, (float4*)bufB, s1, gid, n);
    // 11. prop2 fused with graph pooling
    prop_csr_kernel<true><<<pblocks, 256>>>((const float4*)bufB, nullptr, inv_in, gid, n);
    // 12. out = (poolX/cnt) @ Wfin + (poolD/cnt) * v1 + c0
    final_kernel<<<NGRAPH, 128>>>(out);
}